// round 1
// baseline (speedup 1.0000x reference)
#include <cuda_runtime.h>

#define H 768
#define HEADS 8
#define T_STEPS 3
#define B 128
#define N_ATOM 48
#define NPG 49
#define EPG 144
#define NN (B*NPG)        // 6272 nodes
#define EE (B*EPG)        // 18432 edges
#define HH (HEADS*H)      // 6144
#define G3H (3*H)         // 2304

// ---------------- scratch (__device__ globals; no allocation) ----------------
__device__ float    g_fs[(size_t)NN*HH];
__device__ float    g_fd[(size_t)NN*HH];
__device__ float    g_hbuf0[(size_t)NN*H];
__device__ float    g_hbuf1[(size_t)NN*H];
__device__ float    g_logits[EE*HEADS];
__device__ float    g_att[EE*HEADS];      // ex, then normalized attention
__device__ unsigned g_menc[NN*HEADS];
__device__ float    g_ssum[NN*HEADS];
__device__ float    g_mol[B*H];
__device__ float    g_x[B*H];
__device__ float    g_gi[B*G3H];
__device__ float    g_gh[B*G3H];
__device__ float    g_wT1[(size_t)H*G3H];
__device__ float    g_wT2[(size_t)H*G3H];

// ---------------- utility kernels ----------------
__global__ void k_zero(float* p, int n){ int i = blockIdx.x*blockDim.x + threadIdx.x; if (i < n) p[i] = 0.f; }
__global__ void k_zero_u(unsigned* p, int n){ int i = blockIdx.x*blockDim.x + threadIdx.x; if (i < n) p[i] = 0u; }
__global__ void k_copy(float* d, const float* s, int n){ int i = blockIdx.x*blockDim.x + threadIdx.x; if (i < n) d[i] = s[i]; }

// ---------------- SGEMM: C[M,N] = A[M,K] @ B[K,N] + bias[N], all row-major ----------------
// M % 128 == 0, N % 128 == 0, K % 8 == 0 (guaranteed by problem dims)
#define BM 128
#define BN 128
#define BK 8
__global__ __launch_bounds__(256) void sgemm(const float* __restrict__ A,
                                             const float* __restrict__ Bm,
                                             const float* __restrict__ bias,
                                             float* __restrict__ C,
                                             int M, int N, int K)
{
    __shared__ float As[BK][BM];
    __shared__ float Bs[BK][BN];
    const int bx = blockIdx.x;   // N tile
    const int by = blockIdx.y;   // M tile
    const int tid = threadIdx.x;
    const int tx = tid & 15;     // 0..15 -> 8 cols each
    const int ty = tid >> 4;     // 0..15 -> 8 rows each

    const float* Ap = A + (size_t)by*BM*K;
    const float* Bp = Bm + bx*BN;

    const int aRow  = tid >> 1;          // 0..127
    const int aCol4 = (tid & 1) * 4;     // 0 or 4
    const int bRow  = tid >> 5;          // 0..7
    const int bCol4 = (tid & 31) * 4;    // 0..124

    float acc[8][8];
    #pragma unroll
    for (int i = 0; i < 8; i++)
        #pragma unroll
        for (int j = 0; j < 8; j++) acc[i][j] = 0.f;

    for (int k0 = 0; k0 < K; k0 += BK) {
        float4 av = *(const float4*)(Ap + (size_t)aRow*K + k0 + aCol4);
        As[aCol4+0][aRow] = av.x;
        As[aCol4+1][aRow] = av.y;
        As[aCol4+2][aRow] = av.z;
        As[aCol4+3][aRow] = av.w;
        float4 bv = *(const float4*)(Bp + (size_t)(k0 + bRow)*N + bCol4);
        *(float4*)&Bs[bRow][bCol4] = bv;
        __syncthreads();
        #pragma unroll
        for (int k = 0; k < BK; k++) {
            float a[8], b[8];
            #pragma unroll
            for (int i = 0; i < 8; i++) a[i] = As[k][ty*8 + i];
            #pragma unroll
            for (int j = 0; j < 8; j++) b[j] = Bs[k][tx*8 + j];
            #pragma unroll
            for (int i = 0; i < 8; i++)
                #pragma unroll
                for (int j = 0; j < 8; j++)
                    acc[i][j] += a[i] * b[j];
        }
        __syncthreads();
    }

    #pragma unroll
    for (int i = 0; i < 8; i++) {
        int row = by*BM + ty*8 + i;
        #pragma unroll
        for (int j = 0; j < 8; j++) {
            int col = bx*BN + tx*8 + j;
            C[(size_t)row*N + col] = acc[i][j] + bias[col];
        }
    }
}

// ---------------- transpose: in[R,C] -> out[C,R] (R,C % 32 == 0) ----------------
__global__ void k_transpose(const float* __restrict__ in, float* __restrict__ out, int R, int C)
{
    __shared__ float tile[32][33];
    int c0 = blockIdx.x * 32, r0 = blockIdx.y * 32;
    int tx = threadIdx.x, ty = threadIdx.y; // 32x8
    #pragma unroll
    for (int i = ty; i < 32; i += 8)
        tile[i][tx] = in[(size_t)(r0 + i)*C + c0 + tx];
    __syncthreads();
    #pragma unroll
    for (int i = ty; i < 32; i += 8)
        out[(size_t)(c0 + i)*R + r0 + tx] = tile[tx][i];
}

// ---------------- edge logits + segment max (warp per (edge,head)) ----------------
__global__ __launch_bounds__(256) void k_logits(const float* __restrict__ fs,
                                                const float* __restrict__ fd,
                                                const float* __restrict__ attn_a,
                                                const int* __restrict__ src,
                                                const int* __restrict__ dst,
                                                float* __restrict__ logits,
                                                unsigned* __restrict__ menc)
{
    int e = blockIdx.x;                 // one block per edge
    int h = threadIdx.x >> 5;           // warp = head
    int lane = threadIdx.x & 31;
    int s = src[e], d = dst[e];
    const float* pf = fs + (size_t)s*HH + h*H;
    const float* pd = fd + (size_t)d*HH + h*H;
    const float* pa = attn_a + h*H;
    float acc = 0.f;
    for (int i = lane; i < H; i += 32) {
        float v = pf[i] + pd[i];
        v = v > 0.f ? v : 0.2f * v;     // leaky_relu(0.2)
        acc += v * pa[i];
    }
    #pragma unroll
    for (int o = 16; o; o >>= 1) acc += __shfl_xor_sync(0xffffffffu, acc, o);
    if (lane == 0) {
        logits[e*HEADS + h] = acc;
        unsigned bits = __float_as_uint(acc);
        unsigned enc = (bits & 0x80000000u) ? ~bits : (bits | 0x80000000u);
        atomicMax(&menc[d*HEADS + h], enc);
    }
}

__device__ __forceinline__ float dec_max(unsigned enc)
{
    unsigned bits = (enc & 0x80000000u) ? (enc & 0x7FFFFFFFu) : ~enc;
    return __uint_as_float(bits);
}

__global__ void k_expsum(const float* __restrict__ logits, const unsigned* __restrict__ menc,
                         const int* __restrict__ dst, float* __restrict__ ex, float* __restrict__ ssum)
{
    int i = blockIdx.x*blockDim.x + threadIdx.x;
    if (i >= EE*HEADS) return;
    int e = i / HEADS, h = i - e*HEADS;
    int d = dst[e];
    float m = dec_max(menc[d*HEADS + h]);
    float v = expf(logits[i] - m);
    ex[i] = v;
    atomicAdd(&ssum[d*HEADS + h], v);
}

__global__ void k_norm(float* __restrict__ att, const int* __restrict__ dst, const float* __restrict__ ssum)
{
    int i = blockIdx.x*blockDim.x + threadIdx.x;
    if (i >= EE*HEADS) return;
    int e = i / HEADS, h = i - e*HEADS;
    att[i] = att[i] / ssum[dst[e]*HEADS + h];
}

// ---------------- aggregation: hnext[dst] += (1/8) sum_h a[e,h]*fs[src,h,:] ----------------
__global__ __launch_bounds__(256) void k_aggregate(const float* __restrict__ att,
                                                   const float* __restrict__ fs,
                                                   const int* __restrict__ src,
                                                   const int* __restrict__ dst,
                                                   float* __restrict__ hnext)
{
    int e = blockIdx.x;
    __shared__ float coef[HEADS];
    if (threadIdx.x < HEADS) coef[threadIdx.x] = att[e*HEADS + threadIdx.x] * 0.125f;
    __syncthreads();
    int s = src[e], d = dst[e];
    const float* pf = fs + (size_t)s*HH;
    float* po = hnext + (size_t)d*H;
    for (int i = threadIdx.x; i < H; i += 256) {
        float v = 0.f;
        #pragma unroll
        for (int h = 0; h < HEADS; h++) v += coef[h] * pf[h*H + i];
        atomicAdd(&po[i], v);
    }
}

__global__ void k_attn_out(const float* __restrict__ att, const int* __restrict__ eids,
                           float* __restrict__ out)
{
    int i = blockIdx.x*blockDim.x + threadIdx.x;
    if (i >= B*N_ATOM) return;
    int e = eids[i];
    float s = 0.f;
    #pragma unroll
    for (int h = 0; h < HEADS; h++) s += att[e*HEADS + h];
    out[i] = s * 0.125f;
}

__global__ void k_gather(const float* __restrict__ hn, const int* __restrict__ vnids,
                         float* __restrict__ x)
{
    int i = blockIdx.x*blockDim.x + threadIdx.x;
    if (i >= B*H) return;
    int b = i / H, d = i - b*H;
    x[i] = hn[(size_t)vnids[b]*H + d];
}

__global__ void k_gru(const float* __restrict__ gi, const float* __restrict__ gh,
                      float* __restrict__ mol, float* __restrict__ out_final)
{
    int i = blockIdx.x*blockDim.x + threadIdx.x;
    if (i >= B*H) return;
    int b = i / H, d = i - b*H;
    float ir = gi[b*G3H + d],       hr = gh[b*G3H + d];
    float iz = gi[b*G3H + H + d],   hz = gh[b*G3H + H + d];
    float in_= gi[b*G3H + 2*H + d], hn = gh[b*G3H + 2*H + d];
    float r = 1.f / (1.f + expf(-(ir + hr)));
    float z = 1.f / (1.f + expf(-(iz + hz)));
    float n = tanhf(in_ + r * hn);
    float hp = mol[i];
    float v = (1.f - z) * n + z * hp;
    v = v > 0.f ? v : 0.f;               // relu
    mol[i] = v;
    if (out_final) out_final[i] = v;
}

// ---------------- host ----------------
extern "C" void kernel_launch(void* const* d_in, const int* in_sizes, int n_in,
                              void* d_out, int out_size)
{
    const float* h_nodes  = (const float*)d_in[0];
    const float* mol_feat = (const float*)d_in[1];
    const float* W_src    = (const float*)d_in[2];
    const float* b_src    = (const float*)d_in[3];
    const float* W_dst    = (const float*)d_in[4];
    const float* b_dst    = (const float*)d_in[5];
    const float* attn_a   = (const float*)d_in[6];
    const float* W_ih     = (const float*)d_in[7];
    const float* W_hh     = (const float*)d_in[8];
    const float* b_ih     = (const float*)d_in[9];
    const float* b_hh     = (const float*)d_in[10];
    const int*   src      = (const int*)d_in[11];
    const int*   dst      = (const int*)d_in[12];
    const int*   vnids    = (const int*)d_in[13];
    const int*   eids     = (const int*)d_in[14];
    float* out = (float*)d_out;

    float *fs, *fd, *h0, *h1, *logits, *att, *ssum, *mol, *x, *gi, *gh, *wT1, *wT2;
    unsigned* menc;
    cudaGetSymbolAddress((void**)&fs,     g_fs);
    cudaGetSymbolAddress((void**)&fd,     g_fd);
    cudaGetSymbolAddress((void**)&h0,     g_hbuf0);
    cudaGetSymbolAddress((void**)&h1,     g_hbuf1);
    cudaGetSymbolAddress((void**)&logits, g_logits);
    cudaGetSymbolAddress((void**)&att,    g_att);
    cudaGetSymbolAddress((void**)&menc,   g_menc);
    cudaGetSymbolAddress((void**)&ssum,   g_ssum);
    cudaGetSymbolAddress((void**)&mol,    g_mol);
    cudaGetSymbolAddress((void**)&x,      g_x);
    cudaGetSymbolAddress((void**)&gi,     g_gi);
    cudaGetSymbolAddress((void**)&gh,     g_gh);
    cudaGetSymbolAddress((void**)&wT1,    g_wT1);
    cudaGetSymbolAddress((void**)&wT2,    g_wT2);

    k_copy<<<(B*H + 255)/256, 256>>>(mol, mol_feat, B*H);

    const float* hcur = h_nodes;
    float* hbuf[2] = { h0, h1 };

    for (int t = 0; t < T_STEPS; t++) {
        dim3 gbig(HH/BN, NN/BM);   // 48 x 49
        sgemm<<<gbig, 256>>>(hcur, W_src + (size_t)t*H*HH, b_src + t*HH, fs, NN, HH, H);
        sgemm<<<gbig, 256>>>(hcur, W_dst + (size_t)t*H*HH, b_dst + t*HH, fd, NN, HH, H);

        float* hn = hbuf[t & 1];
        k_zero_u<<<(NN*HEADS + 255)/256, 256>>>(menc, NN*HEADS);
        k_zero  <<<(NN*HEADS + 255)/256, 256>>>(ssum, NN*HEADS);
        k_zero  <<<(NN*H + 255)/256, 256>>>(hn, NN*H);

        k_logits<<<EE, 256>>>(fs, fd, attn_a + (size_t)t*HEADS*H, src, dst, logits, menc);
        k_expsum<<<(EE*HEADS + 255)/256, 256>>>(logits, menc, dst, att, ssum);
        k_norm  <<<(EE*HEADS + 255)/256, 256>>>(att, dst, ssum);
        k_aggregate<<<EE, 256>>>(att, fs, src, dst, hn);
        k_attn_out<<<(B*N_ATOM + 255)/256, 256>>>(att, eids, out + B*H + t*B*N_ATOM);

        // GRU on virtual nodes
        k_gather<<<(B*H + 255)/256, 256>>>(hn, vnids, x);
        k_transpose<<<dim3(H/32, G3H/32), dim3(32, 8)>>>(W_ih + (size_t)t*G3H*H, wT1, G3H, H);
        k_transpose<<<dim3(H/32, G3H/32), dim3(32, 8)>>>(W_hh + (size_t)t*G3H*H, wT2, G3H, H);
        sgemm<<<dim3(G3H/BN, B/BM), 256>>>(x,   wT1, b_ih + t*G3H, gi, B, G3H, H);
        sgemm<<<dim3(G3H/BN, B/BM), 256>>>(mol, wT2, b_hh + t*G3H, gh, B, G3H, H);
        k_gru<<<(B*H + 255)/256, 256>>>(gi, gh, mol, (t == T_STEPS-1) ? out : nullptr);

        hcur = hn;
    }
}

// round 3
// speedup vs baseline: 2.4542x; 2.4542x over previous
#include <cuda_runtime.h>
#include <cuda_bf16.h>
#include <cstdint>

#define H 768
#define HEADS 8
#define T_STEPS 3
#define B 128
#define N_ATOM 48
#define NPG 49
#define EPG 144
#define NN (B*NPG)        // 6272 nodes
#define EE (B*EPG)        // 18432 edges
#define HH (HEADS*H)      // 6144
#define G3H (3*H)         // 2304

// ---------------- scratch (__device__ globals; no allocation) ----------------
__device__ float    g_fs[(size_t)NN*HH];
__device__ float    g_fd[(size_t)NN*HH];
__device__ float    g_hbuf0[(size_t)NN*H];
__device__ float    g_hbuf1[(size_t)NN*H];
__device__ float    g_logits[EE*HEADS];
__device__ float    g_att[EE*HEADS];
__device__ unsigned g_menc[NN*HEADS];
__device__ float    g_ssum[NN*HEADS];
__device__ float    g_mol[B*H];
__device__ float    g_x[B*H];
__device__ float    g_gi[B*G3H];
__device__ float    g_gh[B*G3H];
__device__ float    g_wT1[(size_t)H*G3H];
__device__ float    g_wT2[(size_t)H*G3H];
// bf16 split buffers
__device__ __nv_bfloat16 g_ahi[(size_t)NN*H];
__device__ __nv_bfloat16 g_alo[(size_t)NN*H];
__device__ __nv_bfloat16 g_wsrc_hi[(size_t)HH*H];   // [6144][768] transposed
__device__ __nv_bfloat16 g_wsrc_lo[(size_t)HH*H];
__device__ __nv_bfloat16 g_wdst_hi[(size_t)HH*H];
__device__ __nv_bfloat16 g_wdst_lo[(size_t)HH*H];

// ---------------- PTX helpers (sm_80-class only: ldmatrix / mma.sync / cp.async) ----
__device__ __forceinline__ uint32_t smem_u32(const void* p) {
    uint32_t a;
    asm("{ .reg .u64 t; cvta.to.shared.u64 t, %1; cvt.u32.u64 %0, t; }" : "=r"(a) : "l"(p));
    return a;
}
__device__ __forceinline__ void cp16(uint32_t saddr, const void* gptr) {
    asm volatile("cp.async.cg.shared.global [%0], [%1], 16;" :: "r"(saddr), "l"(gptr));
}
__device__ __forceinline__ void cp_commit() { asm volatile("cp.async.commit_group;"); }
__device__ __forceinline__ void cp_wait1() { asm volatile("cp.async.wait_group 1;"); }
__device__ __forceinline__ void cp_wait0() { asm volatile("cp.async.wait_group 0;"); }
__device__ __forceinline__ void ldm_x4(uint32_t* r, uint32_t addr) {
    asm volatile("ldmatrix.sync.aligned.m8n8.x4.shared.b16 {%0,%1,%2,%3}, [%4];"
                 : "=r"(r[0]), "=r"(r[1]), "=r"(r[2]), "=r"(r[3]) : "r"(addr));
}
__device__ __forceinline__ void ldm_x2(uint32_t* r, uint32_t addr) {
    asm volatile("ldmatrix.sync.aligned.m8n8.x2.shared.b16 {%0,%1}, [%2];"
                 : "=r"(r[0]), "=r"(r[1]) : "r"(addr));
}
__device__ __forceinline__ void mma_bf16(float* c, const uint32_t* a, const uint32_t* b) {
    asm volatile(
        "mma.sync.aligned.m16n8k16.row.col.f32.bf16.bf16.f32 "
        "{%0,%1,%2,%3}, {%4,%5,%6,%7}, {%8,%9}, {%0,%1,%2,%3};"
        : "+f"(c[0]), "+f"(c[1]), "+f"(c[2]), "+f"(c[3])
        : "r"(a[0]), "r"(a[1]), "r"(a[2]), "r"(a[3]), "r"(b[0]), "r"(b[1]));
}

// ---------------- HMMA split-bf16 GEMM ----------------
// C[NN,6144] = (Ahi+Alo)[NN,768] @ (Bhi+Blo)^T + bias ; B stored [6144][768] K-major
#define GM 128
#define GN 128
#define GK 64
#define KCH (H/GK)       // 12
#define ST_SZ (64*1024)  // per-stage: Ahi 16K | Alo 16K | Bhi 16K | Blo 16K
#define OFF_AHI 0
#define OFF_ALO (16*1024)
#define OFF_BHI (32*1024)
#define OFF_BLO (48*1024)
#define TC_SMEM (2*ST_SZ)

__global__ __launch_bounds__(256) void hmma_gemm(
    const __nv_bfloat16* __restrict__ Ahi, const __nv_bfloat16* __restrict__ Alo,
    const __nv_bfloat16* __restrict__ Bhi, const __nv_bfloat16* __restrict__ Blo,
    const float* __restrict__ bias, float* __restrict__ C)
{
    extern __shared__ char smem[];
    const uint32_t sb = smem_u32(smem);
    const int tid = threadIdx.x;
    const int wid = tid >> 5, lane = tid & 31;
    const int wm = wid >> 2, wn = wid & 3;        // 2 x 4 warp grid -> 64 x 32 per warp
    const int m0 = blockIdx.y * GM, n0 = blockIdx.x * GN;

    const char* aH = (const char*)(Ahi + (size_t)m0 * H);
    const char* aL = (const char*)(Alo + (size_t)m0 * H);
    const char* bH = (const char*)(Bhi + (size_t)n0 * H);
    const char* bL = (const char*)(Blo + (size_t)n0 * H);

    float acc[4][4][4];
    #pragma unroll
    for (int i = 0; i < 4; i++)
        #pragma unroll
        for (int j = 0; j < 4; j++)
            #pragma unroll
            for (int q = 0; q < 4; q++) acc[i][j][q] = 0.f;

    // ldmatrix per-lane address components (swizzle: chunk ^= row&7; 128B rows)
    const uint32_t aRowOff = (wm*64 + (lane & 15)) * 128;
    const uint32_t aHiK = lane >> 4;              // 0/1 -> k-halves
    const uint32_t bRowOff = (wn*32 + (lane & 7)) * 128;
    const uint32_t bHiK = (lane >> 3) & 1;
    const uint32_t sw = lane & 7;

    // stage loader: 4 buffers x 1024 16B-chunks, 256 threads x 4 chunks each
    auto load_stage = [&](int stage, int chunk) {
        uint32_t st = sb + stage * ST_SZ;
        int kb = chunk * 128;                      // byte offset in K within a row
        #pragma unroll
        for (int i = 0; i < 4; i++) {
            int id = i * 256 + tid;
            int row = id >> 3, cc = id & 7;
            uint32_t off = row * 128 + ((cc ^ (row & 7)) << 4);
            size_t g = (size_t)row * (H*2) + kb + cc * 16;
            cp16(st + OFF_AHI + off, aH + g);
            cp16(st + OFF_ALO + off, aL + g);
            cp16(st + OFF_BHI + off, bH + g);
            cp16(st + OFF_BLO + off, bL + g);
        }
        cp_commit();
    };

    load_stage(0, 0);

    for (int c = 0; c < KCH; c++) {
        if (c + 1 < KCH) { load_stage((c + 1) & 1, c + 1); cp_wait1(); }
        else             { cp_wait0(); }
        __syncthreads();

        uint32_t st = sb + (c & 1) * ST_SZ;
        #pragma unroll
        for (int ks = 0; ks < 4; ks++) {
            uint32_t ah[4][4], al[4][4], bh[4][2], bl[4][2];
            uint32_t aCh = ((ks*2 + aHiK) ^ sw) << 4;
            #pragma unroll
            for (int mt = 0; mt < 4; mt++) {
                uint32_t ra = aRowOff + mt * 2048 + aCh;
                ldm_x4(ah[mt], st + OFF_AHI + ra);
                ldm_x4(al[mt], st + OFF_ALO + ra);
            }
            uint32_t bCh = ((ks*2 + bHiK) ^ sw) << 4;
            #pragma unroll
            for (int nt = 0; nt < 4; nt++) {
                uint32_t rb = bRowOff + nt * 1024 + bCh;
                ldm_x2(bh[nt], st + OFF_BHI + rb);
                ldm_x2(bl[nt], st + OFF_BLO + rb);
            }
            #pragma unroll
            for (int mt = 0; mt < 4; mt++)
                #pragma unroll
                for (int nt = 0; nt < 4; nt++) {
                    mma_bf16(acc[mt][nt], ah[mt], bh[nt]);
                    mma_bf16(acc[mt][nt], ah[mt], bl[nt]);
                    mma_bf16(acc[mt][nt], al[mt], bh[nt]);
                }
        }
        __syncthreads();
    }

    // epilogue
    const int g = lane >> 2, tq = lane & 3;
    #pragma unroll
    for (int mt = 0; mt < 4; mt++) {
        #pragma unroll
        for (int nt = 0; nt < 4; nt++) {
            int row = m0 + wm*64 + mt*16 + g;
            int col = n0 + wn*32 + nt*8 + tq*2;
            float b0 = bias[col], b1 = bias[col + 1];
            float2 v0 = { acc[mt][nt][0] + b0, acc[mt][nt][1] + b1 };
            float2 v1 = { acc[mt][nt][2] + b0, acc[mt][nt][3] + b1 };
            *(float2*)&C[(size_t)row * HH + col] = v0;
            *(float2*)&C[(size_t)(row + 8) * HH + col] = v1;
        }
    }
}

// ---------------- split / transpose-split conversions ----------------
__global__ void k_splitA(const float* __restrict__ in, __nv_bfloat16* __restrict__ hi,
                         __nv_bfloat16* __restrict__ lo, int n)
{
    int i = blockIdx.x * blockDim.x + threadIdx.x;
    if (i >= n) return;
    float v = in[i];
    __nv_bfloat16 h = __float2bfloat16_rn(v);
    hi[i] = h;
    lo[i] = __float2bfloat16_rn(v - __bfloat162float(h));
}

// W[768][6144] -> hiT/loT [6144][768]
__global__ void k_splitWT(const float* __restrict__ W, __nv_bfloat16* __restrict__ hiT,
                          __nv_bfloat16* __restrict__ loT)
{
    __shared__ float tile[32][33];
    int n0 = blockIdx.x * 32, k0 = blockIdx.y * 32;
    int tx = threadIdx.x, ty = threadIdx.y;
    #pragma unroll
    for (int i = ty; i < 32; i += 8)
        tile[i][tx] = W[(size_t)(k0 + i) * HH + n0 + tx];
    __syncthreads();
    #pragma unroll
    for (int i = ty; i < 32; i += 8) {
        float v = tile[tx][i];
        __nv_bfloat16 h = __float2bfloat16_rn(v);
        hiT[(size_t)(n0 + i) * H + k0 + tx] = h;
        loT[(size_t)(n0 + i) * H + k0 + tx] = __float2bfloat16_rn(v - __bfloat162float(h));
    }
}

// ---------------- utility kernels ----------------
__global__ void k_zero(float* p, int n){ int i = blockIdx.x*blockDim.x + threadIdx.x; if (i < n) p[i] = 0.f; }
__global__ void k_zero_u(unsigned* p, int n){ int i = blockIdx.x*blockDim.x + threadIdx.x; if (i < n) p[i] = 0u; }
__global__ void k_copy(float* d, const float* s, int n){ int i = blockIdx.x*blockDim.x + threadIdx.x; if (i < n) d[i] = s[i]; }

// ---------------- fp32 SGEMM (small GRU GEMMs only) ----------------
#define BM 128
#define BN 128
#define BK 8
__global__ __launch_bounds__(256) void sgemm(const float* __restrict__ A,
                                             const float* __restrict__ Bm,
                                             const float* __restrict__ bias,
                                             float* __restrict__ C,
                                             int M, int N, int K)
{
    __shared__ float As[BK][BM];
    __shared__ float Bs[BK][BN];
    const int bx = blockIdx.x, by = blockIdx.y;
    const int tid = threadIdx.x;
    const int tx = tid & 15, ty = tid >> 4;
    const float* Ap = A + (size_t)by*BM*K;
    const float* Bp = Bm + bx*BN;
    const int aRow = tid >> 1, aCol4 = (tid & 1) * 4;
    const int bRow = tid >> 5, bCol4 = (tid & 31) * 4;
    float acc[8][8];
    #pragma unroll
    for (int i = 0; i < 8; i++)
        #pragma unroll
        for (int j = 0; j < 8; j++) acc[i][j] = 0.f;
    for (int k0 = 0; k0 < K; k0 += BK) {
        float4 av = *(const float4*)(Ap + (size_t)aRow*K + k0 + aCol4);
        As[aCol4+0][aRow] = av.x; As[aCol4+1][aRow] = av.y;
        As[aCol4+2][aRow] = av.z; As[aCol4+3][aRow] = av.w;
        float4 bv = *(const float4*)(Bp + (size_t)(k0 + bRow)*N + bCol4);
        *(float4*)&Bs[bRow][bCol4] = bv;
        __syncthreads();
        #pragma unroll
        for (int k = 0; k < BK; k++) {
            float a[8], b[8];
            #pragma unroll
            for (int i = 0; i < 8; i++) a[i] = As[k][ty*8 + i];
            #pragma unroll
            for (int j = 0; j < 8; j++) b[j] = Bs[k][tx*8 + j];
            #pragma unroll
            for (int i = 0; i < 8; i++)
                #pragma unroll
                for (int j = 0; j < 8; j++)
                    acc[i][j] += a[i] * b[j];
        }
        __syncthreads();
    }
    #pragma unroll
    for (int i = 0; i < 8; i++) {
        int row = by*BM + ty*8 + i;
        #pragma unroll
        for (int j = 0; j < 8; j++) {
            int col = bx*BN + tx*8 + j;
            C[(size_t)row*N + col] = acc[i][j] + bias[col];
        }
    }
}

__global__ void k_transpose(const float* __restrict__ in, float* __restrict__ out, int R, int C)
{
    __shared__ float tile[32][33];
    int c0 = blockIdx.x * 32, r0 = blockIdx.y * 32;
    int tx = threadIdx.x, ty = threadIdx.y;
    #pragma unroll
    for (int i = ty; i < 32; i += 8)
        tile[i][tx] = in[(size_t)(r0 + i)*C + c0 + tx];
    __syncthreads();
    #pragma unroll
    for (int i = ty; i < 32; i += 8)
        out[(size_t)(c0 + i)*R + r0 + tx] = tile[tx][i];
}

// ---------------- edge kernels ----------------
__global__ __launch_bounds__(256) void k_logits(const float* __restrict__ fs,
                                                const float* __restrict__ fd,
                                                const float* __restrict__ attn_a,
                                                const int* __restrict__ src,
                                                const int* __restrict__ dst,
                                                float* __restrict__ logits,
                                                unsigned* __restrict__ menc)
{
    int e = blockIdx.x;
    int h = threadIdx.x >> 5;
    int lane = threadIdx.x & 31;
    int s = src[e], d = dst[e];
    const float* pf = fs + (size_t)s*HH + h*H;
    const float* pd = fd + (size_t)d*HH + h*H;
    const float* pa = attn_a + h*H;
    float acc = 0.f;
    for (int i = lane; i < H; i += 32) {
        float v = pf[i] + pd[i];
        v = v > 0.f ? v : 0.2f * v;
        acc += v * pa[i];
    }
    #pragma unroll
    for (int o = 16; o; o >>= 1) acc += __shfl_xor_sync(0xffffffffu, acc, o);
    if (lane == 0) {
        logits[e*HEADS + h] = acc;
        unsigned bits = __float_as_uint(acc);
        unsigned enc = (bits & 0x80000000u) ? ~bits : (bits | 0x80000000u);
        atomicMax(&menc[d*HEADS + h], enc);
    }
}

__device__ __forceinline__ float dec_max(unsigned enc)
{
    unsigned bits = (enc & 0x80000000u) ? (enc & 0x7FFFFFFFu) : ~enc;
    return __uint_as_float(bits);
}

__global__ void k_expsum(const float* __restrict__ logits, const unsigned* __restrict__ menc,
                         const int* __restrict__ dst, float* __restrict__ ex, float* __restrict__ ssum)
{
    int i = blockIdx.x*blockDim.x + threadIdx.x;
    if (i >= EE*HEADS) return;
    int e = i / HEADS, h = i - e*HEADS;
    int d = dst[e];
    float m = dec_max(menc[d*HEADS + h]);
    float v = expf(logits[i] - m);
    ex[i] = v;
    atomicAdd(&ssum[d*HEADS + h], v);
}

__global__ void k_norm(float* __restrict__ att, const int* __restrict__ dst, const float* __restrict__ ssum)
{
    int i = blockIdx.x*blockDim.x + threadIdx.x;
    if (i >= EE*HEADS) return;
    int e = i / HEADS, h = i - e*HEADS;
    att[i] = att[i] / ssum[dst[e]*HEADS + h];
}

__global__ __launch_bounds__(256) void k_aggregate(const float* __restrict__ att,
                                                   const float* __restrict__ fs,
                                                   const int* __restrict__ src,
                                                   const int* __restrict__ dst,
                                                   float* __restrict__ hnext)
{
    int e = blockIdx.x;
    __shared__ float coef[HEADS];
    if (threadIdx.x < HEADS) coef[threadIdx.x] = att[e*HEADS + threadIdx.x] * 0.125f;
    __syncthreads();
    int s = src[e], d = dst[e];
    const float* pf = fs + (size_t)s*HH;
    float* po = hnext + (size_t)d*H;
    for (int i = threadIdx.x; i < H; i += 256) {
        float v = 0.f;
        #pragma unroll
        for (int h = 0; h < HEADS; h++) v += coef[h] * pf[h*H + i];
        atomicAdd(&po[i], v);
    }
}

__global__ void k_attn_out(const float* __restrict__ att, const int* __restrict__ eids,
                           float* __restrict__ out)
{
    int i = blockIdx.x*blockDim.x + threadIdx.x;
    if (i >= B*N_ATOM) return;
    int e = eids[i];
    float s = 0.f;
    #pragma unroll
    for (int h = 0; h < HEADS; h++) s += att[e*HEADS + h];
    out[i] = s * 0.125f;
}

__global__ void k_gather(const float* __restrict__ hn, const int* __restrict__ vnids,
                         float* __restrict__ x)
{
    int i = blockIdx.x*blockDim.x + threadIdx.x;
    if (i >= B*H) return;
    int b = i / H, d = i - b*H;
    x[i] = hn[(size_t)vnids[b]*H + d];
}

__global__ void k_gru(const float* __restrict__ gi, const float* __restrict__ gh,
                      float* __restrict__ mol, float* __restrict__ out_final)
{
    int i = blockIdx.x*blockDim.x + threadIdx.x;
    if (i >= B*H) return;
    int b = i / H, d = i - b*H;
    float ir = gi[b*G3H + d],       hr = gh[b*G3H + d];
    float iz = gi[b*G3H + H + d],   hz = gh[b*G3H + H + d];
    float in_= gi[b*G3H + 2*H + d], hn = gh[b*G3H + 2*H + d];
    float r = 1.f / (1.f + expf(-(ir + hr)));
    float z = 1.f / (1.f + expf(-(iz + hz)));
    float n = tanhf(in_ + r * hn);
    float hp = mol[i];
    float v = (1.f - z) * n + z * hp;
    v = v > 0.f ? v : 0.f;
    mol[i] = v;
    if (out_final) out_final[i] = v;
}

// ---------------- host ----------------
extern "C" void kernel_launch(void* const* d_in, const int* in_sizes, int n_in,
                              void* d_out, int out_size)
{
    const float* h_nodes  = (const float*)d_in[0];
    const float* mol_feat = (const float*)d_in[1];
    const float* W_src    = (const float*)d_in[2];
    const float* b_src    = (const float*)d_in[3];
    const float* W_dst    = (const float*)d_in[4];
    const float* b_dst    = (const float*)d_in[5];
    const float* attn_a   = (const float*)d_in[6];
    const float* W_ih     = (const float*)d_in[7];
    const float* W_hh     = (const float*)d_in[8];
    const float* b_ih     = (const float*)d_in[9];
    const float* b_hh     = (const float*)d_in[10];
    const int*   src      = (const int*)d_in[11];
    const int*   dst      = (const int*)d_in[12];
    const int*   vnids    = (const int*)d_in[13];
    const int*   eids     = (const int*)d_in[14];
    float* out = (float*)d_out;

    float *fs, *fd, *h0, *h1, *logits, *att, *ssum, *mol, *x, *gi, *gh, *wT1, *wT2;
    unsigned* menc;
    __nv_bfloat16 *ahi, *alo, *wsh, *wsl, *wdh, *wdl;
    cudaGetSymbolAddress((void**)&fs,     g_fs);
    cudaGetSymbolAddress((void**)&fd,     g_fd);
    cudaGetSymbolAddress((void**)&h0,     g_hbuf0);
    cudaGetSymbolAddress((void**)&h1,     g_hbuf1);
    cudaGetSymbolAddress((void**)&logits, g_logits);
    cudaGetSymbolAddress((void**)&att,    g_att);
    cudaGetSymbolAddress((void**)&menc,   g_menc);
    cudaGetSymbolAddress((void**)&ssum,   g_ssum);
    cudaGetSymbolAddress((void**)&mol,    g_mol);
    cudaGetSymbolAddress((void**)&x,      g_x);
    cudaGetSymbolAddress((void**)&gi,     g_gi);
    cudaGetSymbolAddress((void**)&gh,     g_gh);
    cudaGetSymbolAddress((void**)&wT1,    g_wT1);
    cudaGetSymbolAddress((void**)&wT2,    g_wT2);
    cudaGetSymbolAddress((void**)&ahi,    g_ahi);
    cudaGetSymbolAddress((void**)&alo,    g_alo);
    cudaGetSymbolAddress((void**)&wsh,    g_wsrc_hi);
    cudaGetSymbolAddress((void**)&wsl,    g_wsrc_lo);
    cudaGetSymbolAddress((void**)&wdh,    g_wdst_hi);
    cudaGetSymbolAddress((void**)&wdl,    g_wdst_lo);

    cudaFuncSetAttribute(hmma_gemm, cudaFuncAttributeMaxDynamicSharedMemorySize, TC_SMEM);

    k_copy<<<(B*H + 255)/256, 256>>>(mol, mol_feat, B*H);

    const float* hcur = h_nodes;
    float* hbuf[2] = { h0, h1 };

    for (int t = 0; t < T_STEPS; t++) {
        // split conversions
        k_splitA<<<(NN*H + 255)/256, 256>>>(hcur, ahi, alo, NN*H);
        dim3 wtg(HH/32, H/32);
        k_splitWT<<<wtg, dim3(32, 8)>>>(W_src + (size_t)t*H*HH, wsh, wsl);
        k_splitWT<<<wtg, dim3(32, 8)>>>(W_dst + (size_t)t*H*HH, wdh, wdl);

        // tensor-core GEMMs: fs, fd
        dim3 gg(HH/GN, NN/GM);   // 48 x 49
        hmma_gemm<<<gg, 256, TC_SMEM>>>(ahi, alo, wsh, wsl, b_src + t*HH, fs);
        hmma_gemm<<<gg, 256, TC_SMEM>>>(ahi, alo, wdh, wdl, b_dst + t*HH, fd);

        float* hn = hbuf[t & 1];
        k_zero_u<<<(NN*HEADS + 255)/256, 256>>>(menc, NN*HEADS);
        k_zero  <<<(NN*HEADS + 255)/256, 256>>>(ssum, NN*HEADS);
        k_zero  <<<(NN*H + 255)/256, 256>>>(hn, NN*H);

        k_logits<<<EE, 256>>>(fs, fd, attn_a + (size_t)t*HEADS*H, src, dst, logits, menc);
        k_expsum<<<(EE*HEADS + 255)/256, 256>>>(logits, menc, dst, att, ssum);
        k_norm  <<<(EE*HEADS + 255)/256, 256>>>(att, dst, ssum);
        k_aggregate<<<EE, 256>>>(att, fs, src, dst, hn);
        k_attn_out<<<(B*N_ATOM + 255)/256, 256>>>(att, eids, out + B*H + t*B*N_ATOM);

        // GRU on virtual nodes (fp32, tiny)
        k_gather<<<(B*H + 255)/256, 256>>>(hn, vnids, x);
        k_transpose<<<dim3(H/32, G3H/32), dim3(32, 8)>>>(W_ih + (size_t)t*G3H*H, wT1, G3H, H);
        k_transpose<<<dim3(H/32, G3H/32), dim3(32, 8)>>>(W_hh + (size_t)t*G3H*H, wT2, G3H, H);
        sgemm<<<dim3(G3H/BN, B/BM), 256>>>(x,   wT1, b_ih + t*G3H, gi, B, G3H, H);
        sgemm<<<dim3(G3H/BN, B/BM), 256>>>(mol, wT2, b_hh + t*G3H, gh, B, G3H, H);
        k_gru<<<(B*H + 255)/256, 256>>>(gi, gh, mol, (t == T_STEPS-1) ? out : nullptr);

        hcur = hn;
    }
}

// round 4
// speedup vs baseline: 2.4785x; 1.0099x over previous
#include <cuda_runtime.h>
#include <cuda_bf16.h>
#include <cstdint>

#define H 768
#define HEADS 8
#define T_STEPS 3
#define B 128
#define N_ATOM 48
#define NPG 49
#define EPG 144
#define NN (B*NPG)        // 6272 nodes
#define EE (B*EPG)        // 18432 edges
#define HH (HEADS*H)      // 6144
#define NH2 (2*HH)        // 12288 combined fs|fd columns
#define G3H (3*H)         // 2304

// ---------------- scratch (__device__ globals; no allocation) ----------------
__device__ float    g_f[(size_t)NN*NH2];      // combined [fs | fd] per node
__device__ float    g_hbuf0[(size_t)NN*H];
__device__ float    g_hbuf1[(size_t)NN*H];
__device__ float    g_logits[EE*HEADS];
__device__ float    g_att[EE*HEADS];
__device__ float    g_mol[B*H];
__device__ float    g_x[B*H];
__device__ float    g_gi[B*G3H];
__device__ float    g_gh[B*G3H];
__device__ float    g_wT1[(size_t)H*G3H];
__device__ float    g_wT2[(size_t)H*G3H];
__device__ float    g_bias2[NH2];
// bf16 split buffers
__device__ __nv_bfloat16 g_ahi[(size_t)NN*H];
__device__ __nv_bfloat16 g_alo[(size_t)NN*H];
__device__ __nv_bfloat16 g_whi[(size_t)NH2*H];  // [12288][768] (W_src^T rows 0..6143, W_dst^T rows 6144..)
__device__ __nv_bfloat16 g_wlo[(size_t)NH2*H];
// CSR
__device__ int g_offA[NN];
__device__ int g_degA[NN];
__device__ int g_eix[EE];

// ---------------- PTX helpers ----------------
__device__ __forceinline__ uint32_t smem_u32(const void* p) {
    uint32_t a;
    asm("{ .reg .u64 t; cvta.to.shared.u64 t, %1; cvt.u32.u64 %0, t; }" : "=r"(a) : "l"(p));
    return a;
}
__device__ __forceinline__ void cp16(uint32_t saddr, const void* gptr) {
    asm volatile("cp.async.cg.shared.global [%0], [%1], 16;" :: "r"(saddr), "l"(gptr));
}
__device__ __forceinline__ void cp_commit() { asm volatile("cp.async.commit_group;"); }
__device__ __forceinline__ void cp_wait1() { asm volatile("cp.async.wait_group 1;"); }
__device__ __forceinline__ void cp_wait0() { asm volatile("cp.async.wait_group 0;"); }
__device__ __forceinline__ void ldm_x4(uint32_t* r, uint32_t addr) {
    asm volatile("ldmatrix.sync.aligned.m8n8.x4.shared.b16 {%0,%1,%2,%3}, [%4];"
                 : "=r"(r[0]), "=r"(r[1]), "=r"(r[2]), "=r"(r[3]) : "r"(addr));
}
__device__ __forceinline__ void ldm_x2(uint32_t* r, uint32_t addr) {
    asm volatile("ldmatrix.sync.aligned.m8n8.x2.shared.b16 {%0,%1}, [%2];"
                 : "=r"(r[0]), "=r"(r[1]) : "r"(addr));
}
__device__ __forceinline__ void mma_bf16(float* c, const uint32_t* a, const uint32_t* b) {
    asm volatile(
        "mma.sync.aligned.m16n8k16.row.col.f32.bf16.bf16.f32 "
        "{%0,%1,%2,%3}, {%4,%5,%6,%7}, {%8,%9}, {%0,%1,%2,%3};"
        : "+f"(c[0]), "+f"(c[1]), "+f"(c[2]), "+f"(c[3])
        : "r"(a[0]), "r"(a[1]), "r"(a[2]), "r"(a[3]), "r"(b[0]), "r"(b[1]));
}

// ---------------- HMMA split-bf16 GEMM (combined fs|fd) ----------------
// f[NN,12288] = (Ahi+Alo)[NN,768] @ (Whi+Wlo)^T + bias2 ; W stored [12288][768] K-major
#define GM 128
#define GN 128
#define GK 32
#define KCH (H/GK)       // 24
#define ST_SZ 32768      // per-stage: Ahi 8K | Alo 8K | Bhi 8K | Blo 8K
#define OFF_AHI 0
#define OFF_ALO 8192
#define OFF_BHI 16384
#define OFF_BLO 24576
#define TC_SMEM (3*ST_SZ)

__global__ __launch_bounds__(256, 2) void hmma_gemm(
    const __nv_bfloat16* __restrict__ Ahi, const __nv_bfloat16* __restrict__ Alo,
    const __nv_bfloat16* __restrict__ Whi, const __nv_bfloat16* __restrict__ Wlo,
    const float* __restrict__ bias, float* __restrict__ C)
{
    extern __shared__ char smem[];
    const uint32_t sb = smem_u32(smem);
    const int tid = threadIdx.x;
    const int wid = tid >> 5, lane = tid & 31;
    const int wm = wid >> 2, wn = wid & 3;        // 2 x 4 warp grid -> 64 x 32 per warp
    const int m0 = blockIdx.y * GM, n0 = blockIdx.x * GN;

    const char* aH = (const char*)(Ahi + (size_t)m0 * H);
    const char* aL = (const char*)(Alo + (size_t)m0 * H);
    const char* bH = (const char*)(Whi + (size_t)n0 * H);
    const char* bL = (const char*)(Wlo + (size_t)n0 * H);

    float acc[4][4][4];
    #pragma unroll
    for (int i = 0; i < 4; i++)
        #pragma unroll
        for (int j = 0; j < 4; j++)
            #pragma unroll
            for (int q = 0; q < 4; q++) acc[i][j][q] = 0.f;

    // stage loader: 4 buffers x 512 16B-chunks (128 rows x 4 chunks of 16B)
    auto load_stage = [&](int stage, int chunk) {
        uint32_t st = sb + stage * ST_SZ;
        int kb = chunk * 64;                 // byte offset in K within a row
        #pragma unroll
        for (int i = 0; i < 8; i++) {
            int buf = i >> 1;                // 2 iters per buffer
            int rem = ((i & 1) << 8) + tid;  // 0..511
            int row = rem >> 2, ch = rem & 3;
            uint32_t off = (uint32_t)buf * 8192 + row * 64 + (((ch ^ ((row >> 1) & 3))) << 4);
            const char* base = (buf == 0) ? aH : (buf == 1) ? aL : (buf == 2) ? bH : bL;
            cp16(st + off, base + (size_t)row * (H*2) + kb + ch * 16);
        }
        cp_commit();
    };

    load_stage(0, 0);
    load_stage(1, 1);

    const int arow = lane & 15;
    const int akh  = lane >> 4;              // 0/1
    const int brow = lane & 7;
    const int bkh  = (lane >> 3) & 1;

    for (int c = 0; c < KCH; c++) {
        if (c + 1 < KCH) cp_wait1(); else cp_wait0();
        __syncthreads();
        if (c + 2 < KCH) load_stage((c + 2) % 3, c + 2);

        uint32_t st = sb + (c % 3) * ST_SZ;
        #pragma unroll
        for (int j = 0; j < 2; j++) {        // two k16 steps per chunk
            uint32_t ah[4][4], al[4][4];
            int ka = j * 2 + akh;
            #pragma unroll
            for (int mt = 0; mt < 4; mt++) {
                int row = wm * 64 + mt * 16 + arow;
                uint32_t off = row * 64 + ((ka ^ ((row >> 1) & 3)) << 4);
                ldm_x4(ah[mt], st + OFF_AHI + off);
                ldm_x4(al[mt], st + OFF_ALO + off);
            }
            int kb2 = j * 2 + bkh;
            #pragma unroll
            for (int nt = 0; nt < 4; nt++) {
                uint32_t bh[2], bl[2];
                int row = wn * 32 + nt * 8 + brow;
                uint32_t off = row * 64 + ((kb2 ^ ((row >> 1) & 3)) << 4);
                ldm_x2(bh, st + OFF_BHI + off);
                ldm_x2(bl, st + OFF_BLO + off);
                #pragma unroll
                for (int mt = 0; mt < 4; mt++) {
                    mma_bf16(acc[mt][nt], ah[mt], bh);
                    mma_bf16(acc[mt][nt], ah[mt], bl);
                    mma_bf16(acc[mt][nt], al[mt], bh);
                }
            }
        }
    }

    // epilogue
    const int g = lane >> 2, tq = lane & 3;
    #pragma unroll
    for (int mt = 0; mt < 4; mt++) {
        #pragma unroll
        for (int nt = 0; nt < 4; nt++) {
            int row = m0 + wm*64 + mt*16 + g;
            int col = n0 + wn*32 + nt*8 + tq*2;
            float b0 = bias[col], b1 = bias[col + 1];
            float2 v0 = { acc[mt][nt][0] + b0, acc[mt][nt][1] + b1 };
            float2 v1 = { acc[mt][nt][2] + b0, acc[mt][nt][3] + b1 };
            *(float2*)&C[(size_t)row * NH2 + col] = v0;
            *(float2*)&C[(size_t)(row + 8) * NH2 + col] = v1;
        }
    }
}

// ---------------- conversions ----------------
__global__ void k_splitA(const float* __restrict__ in, __nv_bfloat16* __restrict__ hi,
                         __nv_bfloat16* __restrict__ lo, int n)
{
    int i = blockIdx.x * blockDim.x + threadIdx.x;
    if (i >= n) return;
    float v = in[i];
    __nv_bfloat16 h = __float2bfloat16_rn(v);
    hi[i] = h;
    lo[i] = __float2bfloat16_rn(v - __bfloat162float(h));
}

// W[768][6144] -> rows [rowoff..rowoff+6144) of combined hiT/loT [12288][768]
__global__ void k_splitWT(const float* __restrict__ W, __nv_bfloat16* __restrict__ hiT,
                          __nv_bfloat16* __restrict__ loT, int rowoff)
{
    __shared__ float tile[32][33];
    int n0 = blockIdx.x * 32, k0 = blockIdx.y * 32;
    int tx = threadIdx.x, ty = threadIdx.y;
    #pragma unroll
    for (int i = ty; i < 32; i += 8)
        tile[i][tx] = W[(size_t)(k0 + i) * HH + n0 + tx];
    __syncthreads();
    #pragma unroll
    for (int i = ty; i < 32; i += 8) {
        float v = tile[tx][i];
        __nv_bfloat16 h = __float2bfloat16_rn(v);
        size_t o = (size_t)(rowoff + n0 + i) * H + k0 + tx;
        hiT[o] = h;
        loT[o] = __float2bfloat16_rn(v - __bfloat162float(h));
    }
}

__global__ void k_bias2(const float* __restrict__ bs, const float* __restrict__ bd,
                        float* __restrict__ b2)
{
    int i = blockIdx.x * blockDim.x + threadIdx.x;
    if (i < HH) b2[i] = bs[i];
    else if (i < NH2) b2[i] = bd[i - HH];
}

__global__ void k_copy(float* d, const float* s, int n){ int i = blockIdx.x*blockDim.x + threadIdx.x; if (i < n) d[i] = s[i]; }

// ---------------- CSR build (per graph; deterministic) ----------------
__global__ void k_csr(const int* __restrict__ dst, int* __restrict__ offA,
                      int* __restrict__ degA, int* __restrict__ eix)
{
    __shared__ int cnt[NPG];
    __shared__ int basep[NPG];
    int g = blockIdx.x, tid = threadIdx.x;
    if (tid < NPG) cnt[tid] = 0;
    __syncthreads();
    if (tid < EPG) {
        int e = g * EPG + tid;
        atomicAdd(&cnt[dst[e] - g * NPG], 1);
    }
    __syncthreads();
    if (tid == 0) {
        int run = g * EPG;
        for (int i = 0; i < NPG; i++) {
            basep[i] = run;
            offA[g * NPG + i] = run;
            degA[g * NPG + i] = cnt[i];
            run += cnt[i];
        }
        // deterministic scatter in edge-index order
        for (int j = 0; j < EPG; j++) {
            int e = g * EPG + j;
            int dl = dst[e] - g * NPG;
            eix[basep[dl]++] = e;
        }
    }
}

// ---------------- edge kernels ----------------
__global__ __launch_bounds__(256) void k_logits(const float* __restrict__ f,
                                                const float* __restrict__ attn_a,
                                                const int* __restrict__ src,
                                                const int* __restrict__ dst,
                                                float* __restrict__ logits)
{
    int e = blockIdx.x;
    int h = threadIdx.x >> 5;
    int lane = threadIdx.x & 31;
    int s = src[e], d = dst[e];
    const float4* pf = (const float4*)(f + (size_t)s*NH2 + h*H);
    const float4* pd = (const float4*)(f + (size_t)d*NH2 + HH + h*H);
    const float4* pa = (const float4*)(attn_a + h*H);
    float acc = 0.f;
    #pragma unroll
    for (int i = lane; i < H/4; i += 32) {
        float4 a = pf[i], b = pd[i], w = pa[i];
        float v;
        v = a.x + b.x; v = v > 0.f ? v : 0.2f*v; acc += v * w.x;
        v = a.y + b.y; v = v > 0.f ? v : 0.2f*v; acc += v * w.y;
        v = a.z + b.z; v = v > 0.f ? v : 0.2f*v; acc += v * w.z;
        v = a.w + b.w; v = v > 0.f ? v : 0.2f*v; acc += v * w.w;
    }
    #pragma unroll
    for (int o = 16; o; o >>= 1) acc += __shfl_xor_sync(0xffffffffu, acc, o);
    if (lane == 0) logits[e*HEADS + h] = acc;
}

// warp per node: softmax over incoming edges, per head
__global__ __launch_bounds__(256) void k_softmax(const float* __restrict__ logits,
                                                 const int* __restrict__ offA,
                                                 const int* __restrict__ degA,
                                                 const int* __restrict__ eix,
                                                 float* __restrict__ att)
{
    int n = blockIdx.x * 8 + (threadIdx.x >> 5);
    int lane = threadIdx.x & 31;
    int off = offA[n], deg = degA[n];
    int h = lane & 7, grp = lane >> 3;       // 4 edge groups
    float m = -1e30f;
    for (int j = grp; j < deg; j += 4)
        m = fmaxf(m, logits[eix[off + j]*HEADS + h]);
    m = fmaxf(m, __shfl_xor_sync(0xffffffffu, m, 8));
    m = fmaxf(m, __shfl_xor_sync(0xffffffffu, m, 16));
    float s = 0.f;
    for (int j = grp; j < deg; j += 4)
        s += expf(logits[eix[off + j]*HEADS + h] - m);
    s += __shfl_xor_sync(0xffffffffu, s, 8);
    s += __shfl_xor_sync(0xffffffffu, s, 16);
    float inv = 1.f / s;
    for (int j = grp; j < deg; j += 4) {
        int ei = eix[off + j];
        att[ei*HEADS + h] = expf(logits[ei*HEADS + h] - m) * inv;
    }
}

// block per node: hn[n] = (1/8) sum_j sum_h att[e_j,h] * fs[src_j, h*H:]
__global__ __launch_bounds__(256) void k_aggregate(const float* __restrict__ att,
                                                   const float* __restrict__ f,
                                                   const int* __restrict__ src,
                                                   const int* __restrict__ offA,
                                                   const int* __restrict__ degA,
                                                   const int* __restrict__ eix,
                                                   float* __restrict__ hnext)
{
    __shared__ float coef[96*HEADS];
    __shared__ int   srcs[96];
    int n = blockIdx.x, tid = threadIdx.x;
    int off = offA[n], deg = degA[n];
    for (int idx = tid; idx < deg*HEADS; idx += 256) {
        int j = idx >> 3, h = idx & 7;
        coef[idx] = att[eix[off + j]*HEADS + h] * 0.125f;
    }
    if (tid < deg) srcs[tid] = src[eix[off + tid]];
    __syncthreads();
    #pragma unroll
    for (int i = tid; i < H; i += 256) {
        float v = 0.f;
        for (int j = 0; j < deg; j++) {
            const float* p = f + (size_t)srcs[j]*NH2 + i;
            const float* cj = coef + j*HEADS;
            #pragma unroll
            for (int h = 0; h < HEADS; h++) v += cj[h] * p[h*H];
        }
        hnext[(size_t)n*H + i] = v;
    }
}

__global__ void k_attn_out(const float* __restrict__ att, const int* __restrict__ eids,
                           float* __restrict__ out)
{
    int i = blockIdx.x*blockDim.x + threadIdx.x;
    if (i >= B*N_ATOM) return;
    int e = eids[i];
    float s = 0.f;
    #pragma unroll
    for (int h = 0; h < HEADS; h++) s += att[e*HEADS + h];
    out[i] = s * 0.125f;
}

__global__ void k_gather(const float* __restrict__ hn, const int* __restrict__ vnids,
                         float* __restrict__ x)
{
    int i = blockIdx.x*blockDim.x + threadIdx.x;
    if (i >= B*H) return;
    int b = i / H, d = i - b*H;
    x[i] = hn[(size_t)vnids[b]*H + d];
}

// ---------------- fp32 SGEMM (small GRU GEMMs only) ----------------
#define BM 128
#define BN 128
#define BK 8
__global__ __launch_bounds__(256) void sgemm(const float* __restrict__ A,
                                             const float* __restrict__ Bm,
                                             const float* __restrict__ bias,
                                             float* __restrict__ C,
                                             int M, int N, int K)
{
    __shared__ float As[BK][BM];
    __shared__ float Bs[BK][BN];
    const int bx = blockIdx.x, by = blockIdx.y;
    const int tid = threadIdx.x;
    const int tx = tid & 15, ty = tid >> 4;
    const float* Ap = A + (size_t)by*BM*K;
    const float* Bp = Bm + bx*BN;
    const int aRow = tid >> 1, aCol4 = (tid & 1) * 4;
    const int bRow = tid >> 5, bCol4 = (tid & 31) * 4;
    float acc[8][8];
    #pragma unroll
    for (int i = 0; i < 8; i++)
        #pragma unroll
        for (int j = 0; j < 8; j++) acc[i][j] = 0.f;
    for (int k0 = 0; k0 < K; k0 += BK) {
        float4 av = *(const float4*)(Ap + (size_t)aRow*K + k0 + aCol4);
        As[aCol4+0][aRow] = av.x; As[aCol4+1][aRow] = av.y;
        As[aCol4+2][aRow] = av.z; As[aCol4+3][aRow] = av.w;
        float4 bv = *(const float4*)(Bp + (size_t)(k0 + bRow)*N + bCol4);
        *(float4*)&Bs[bRow][bCol4] = bv;
        __syncthreads();
        #pragma unroll
        for (int k = 0; k < BK; k++) {
            float a[8], b[8];
            #pragma unroll
            for (int i = 0; i < 8; i++) a[i] = As[k][ty*8 + i];
            #pragma unroll
            for (int j = 0; j < 8; j++) b[j] = Bs[k][tx*8 + j];
            #pragma unroll
            for (int i = 0; i < 8; i++)
                #pragma unroll
                for (int j = 0; j < 8; j++)
                    acc[i][j] += a[i] * b[j];
        }
        __syncthreads();
    }
    #pragma unroll
    for (int i = 0; i < 8; i++) {
        int row = by*BM + ty*8 + i;
        #pragma unroll
        for (int j = 0; j < 8; j++) {
            int col = bx*BN + tx*8 + j;
            C[(size_t)row*N + col] = acc[i][j] + bias[col];
        }
    }
}

__global__ void k_transpose(const float* __restrict__ in, float* __restrict__ out, int R, int C)
{
    __shared__ float tile[32][33];
    int c0 = blockIdx.x * 32, r0 = blockIdx.y * 32;
    int tx = threadIdx.x, ty = threadIdx.y;
    #pragma unroll
    for (int i = ty; i < 32; i += 8)
        tile[i][tx] = in[(size_t)(r0 + i)*C + c0 + tx];
    __syncthreads();
    #pragma unroll
    for (int i = ty; i < 32; i += 8)
        out[(size_t)(c0 + i)*R + r0 + tx] = tile[tx][i];
}

__global__ void k_gru(const float* __restrict__ gi, const float* __restrict__ gh,
                      float* __restrict__ mol, float* __restrict__ out_final)
{
    int i = blockIdx.x*blockDim.x + threadIdx.x;
    if (i >= B*H) return;
    int b = i / H, d = i - b*H;
    float ir = gi[b*G3H + d],       hr = gh[b*G3H + d];
    float iz = gi[b*G3H + H + d],   hz = gh[b*G3H + H + d];
    float in_= gi[b*G3H + 2*H + d], hn = gh[b*G3H + 2*H + d];
    float r = 1.f / (1.f + expf(-(ir + hr)));
    float z = 1.f / (1.f + expf(-(iz + hz)));
    float n = tanhf(in_ + r * hn);
    float hp = mol[i];
    float v = (1.f - z) * n + z * hp;
    v = v > 0.f ? v : 0.f;
    mol[i] = v;
    if (out_final) out_final[i] = v;
}

// ---------------- host ----------------
extern "C" void kernel_launch(void* const* d_in, const int* in_sizes, int n_in,
                              void* d_out, int out_size)
{
    const float* h_nodes  = (const float*)d_in[0];
    const float* mol_feat = (const float*)d_in[1];
    const float* W_src    = (const float*)d_in[2];
    const float* b_src    = (const float*)d_in[3];
    const float* W_dst    = (const float*)d_in[4];
    const float* b_dst    = (const float*)d_in[5];
    const float* attn_a   = (const float*)d_in[6];
    const float* W_ih     = (const float*)d_in[7];
    const float* W_hh     = (const float*)d_in[8];
    const float* b_ih     = (const float*)d_in[9];
    const float* b_hh     = (const float*)d_in[10];
    const int*   src      = (const int*)d_in[11];
    const int*   dst      = (const int*)d_in[12];
    const int*   vnids    = (const int*)d_in[13];
    const int*   eids     = (const int*)d_in[14];
    float* out = (float*)d_out;

    float *f, *h0, *h1, *logits, *att, *mol, *x, *gi, *gh, *wT1, *wT2, *bias2;
    __nv_bfloat16 *ahi, *alo, *whi, *wlo;
    int *offA, *degA, *eixp;
    cudaGetSymbolAddress((void**)&f,      g_f);
    cudaGetSymbolAddress((void**)&h0,     g_hbuf0);
    cudaGetSymbolAddress((void**)&h1,     g_hbuf1);
    cudaGetSymbolAddress((void**)&logits, g_logits);
    cudaGetSymbolAddress((void**)&att,    g_att);
    cudaGetSymbolAddress((void**)&mol,    g_mol);
    cudaGetSymbolAddress((void**)&x,      g_x);
    cudaGetSymbolAddress((void**)&gi,     g_gi);
    cudaGetSymbolAddress((void**)&gh,     g_gh);
    cudaGetSymbolAddress((void**)&wT1,    g_wT1);
    cudaGetSymbolAddress((void**)&wT2,    g_wT2);
    cudaGetSymbolAddress((void**)&bias2,  g_bias2);
    cudaGetSymbolAddress((void**)&ahi,    g_ahi);
    cudaGetSymbolAddress((void**)&alo,    g_alo);
    cudaGetSymbolAddress((void**)&whi,    g_whi);
    cudaGetSymbolAddress((void**)&wlo,    g_wlo);
    cudaGetSymbolAddress((void**)&offA,   g_offA);
    cudaGetSymbolAddress((void**)&degA,   g_degA);
    cudaGetSymbolAddress((void**)&eixp,   g_eix);

    cudaFuncSetAttribute(hmma_gemm, cudaFuncAttributeMaxDynamicSharedMemorySize, TC_SMEM);

    k_copy<<<(B*H + 255)/256, 256>>>(mol, mol_feat, B*H);
    k_csr<<<B, 160>>>(dst, offA, degA, eixp);

    const float* hcur = h_nodes;
    float* hbuf[2] = { h0, h1 };

    for (int t = 0; t < T_STEPS; t++) {
        // split conversions into combined weight buffer
        k_splitA<<<(NN*H + 255)/256, 256>>>(hcur, ahi, alo, NN*H);
        dim3 wtg(HH/32, H/32);
        k_splitWT<<<wtg, dim3(32, 8)>>>(W_src + (size_t)t*H*HH, whi, wlo, 0);
        k_splitWT<<<wtg, dim3(32, 8)>>>(W_dst + (size_t)t*H*HH, whi, wlo, HH);
        k_bias2<<<(NH2 + 255)/256, 256>>>(b_src + t*HH, b_dst + t*HH, bias2);

        // one combined tensor-core GEMM: f = [fs | fd]
        dim3 gg(NH2/GN, NN/GM);   // 96 x 49
        hmma_gemm<<<gg, 256, TC_SMEM>>>(ahi, alo, whi, wlo, bias2, f);

        float* hn = hbuf[t & 1];
        k_logits<<<EE, 256>>>(f, attn_a + (size_t)t*HEADS*H, src, dst, logits);
        k_softmax<<<NN/8, 256>>>(logits, offA, degA, eixp, att);
        k_aggregate<<<NN, 256>>>(att, f, src, offA, degA, eixp, hn);
        k_attn_out<<<(B*N_ATOM + 255)/256, 256>>>(att, eids, out + B*H + t*B*N_ATOM);

        // GRU on virtual nodes (fp32, tiny)
        k_gather<<<(B*H + 255)/256, 256>>>(hn, vnids, x);
        k_transpose<<<dim3(H/32, G3H/32), dim3(32, 8)>>>(W_ih + (size_t)t*G3H*H, wT1, G3H, H);
        k_transpose<<<dim3(H/32, G3H/32), dim3(32, 8)>>>(W_hh + (size_t)t*G3H*H, wT2, G3H, H);
        sgemm<<<dim3(G3H/BN, B/BM), 256>>>(x,   wT1, b_ih + t*G3H, gi, B, G3H, H);
        sgemm<<<dim3(G3H/BN, B/BM), 256>>>(mol, wT2, b_hh + t*G3H, gh, B, G3H, H);
        k_gru<<<(B*H + 255)/256, 256>>>(gi, gh, mol, (t == T_STEPS-1) ? out : nullptr);

        hcur = hn;
    }
}

// round 6
// speedup vs baseline: 2.9470x; 1.1890x over previous
#include <cuda_runtime.h>
#include <cuda_fp16.h>
#include <cstdint>

#define H 768
#define HEADS 8
#define T_STEPS 3
#define B 128
#define N_ATOM 48
#define NPG 49
#define EPG 144
#define NN (B*NPG)        // 6272 nodes
#define EE (B*EPG)        // 18432 edges
#define HH (HEADS*H)      // 6144
#define NH2 (2*HH)        // 12288 combined fs|fd columns
#define G3H (3*H)         // 2304

// ---------------- scratch (__device__ globals; no allocation) ----------------
__device__ __half   g_f[(size_t)NN*NH2];      // combined [fs | fd] per node, fp16
__device__ float    g_hbuf0[(size_t)NN*H];
__device__ float    g_hbuf1[(size_t)NN*H];
__device__ float    g_logits[EE*HEADS];
__device__ float    g_att[EE*HEADS];
__device__ float    g_mol[B*H];
__device__ float    g_x[B*H];
__device__ float    g_gi[B*G3H];
__device__ float    g_gh[B*G3H];
__device__ float    g_wT1[(size_t)H*G3H];
__device__ float    g_wT2[(size_t)H*G3H];
__device__ float    g_bias2[NH2];
// fp16 split buffers
__device__ __half g_ahi[(size_t)NN*H];
__device__ __half g_alo[(size_t)NN*H];
__device__ __half g_wh[(size_t)NH2*H];   // [12288][768] transposed weights fp16
// CSR
__device__ int g_offA[NN];
__device__ int g_degA[NN];
__device__ int g_eix[EE];

// ---------------- PTX helpers ----------------
__device__ __forceinline__ uint32_t smem_u32(const void* p) {
    uint32_t a;
    asm("{ .reg .u64 t; cvta.to.shared.u64 t, %1; cvt.u32.u64 %0, t; }" : "=r"(a) : "l"(p));
    return a;
}
__device__ __forceinline__ void cp16(uint32_t saddr, const void* gptr) {
    asm volatile("cp.async.cg.shared.global [%0], [%1], 16;" :: "r"(saddr), "l"(gptr));
}
__device__ __forceinline__ void cp_commit() { asm volatile("cp.async.commit_group;"); }
__device__ __forceinline__ void cp_wait2() { asm volatile("cp.async.wait_group 2;"); }
__device__ __forceinline__ void cp_wait1() { asm volatile("cp.async.wait_group 1;"); }
__device__ __forceinline__ void cp_wait0() { asm volatile("cp.async.wait_group 0;"); }
__device__ __forceinline__ void ldm_x4(uint32_t* r, uint32_t addr) {
    asm volatile("ldmatrix.sync.aligned.m8n8.x4.shared.b16 {%0,%1,%2,%3}, [%4];"
                 : "=r"(r[0]), "=r"(r[1]), "=r"(r[2]), "=r"(r[3]) : "r"(addr));
}
__device__ __forceinline__ void ldm_x2(uint32_t* r, uint32_t addr) {
    asm volatile("ldmatrix.sync.aligned.m8n8.x2.shared.b16 {%0,%1}, [%2];"
                 : "=r"(r[0]), "=r"(r[1]) : "r"(addr));
}
__device__ __forceinline__ void mma_f16(float* c, const uint32_t* a, const uint32_t* b) {
    asm volatile(
        "mma.sync.aligned.m16n8k16.row.col.f32.f16.f16.f32 "
        "{%0,%1,%2,%3}, {%4,%5,%6,%7}, {%8,%9}, {%0,%1,%2,%3};"
        : "+f"(c[0]), "+f"(c[1]), "+f"(c[2]), "+f"(c[3])
        : "r"(a[0]), "r"(a[1]), "r"(a[2]), "r"(a[3]), "r"(b[0]), "r"(b[1]));
}

// ---------------- HMMA 2-pass split-fp16 GEMM (combined fs|fd) ----------------
// f[NN,12288] = (Ahi+Alo)[NN,768] @ Wh^T + bias2 ; W stored [12288][768] K-major fp16
#define GM 128
#define GN 128
#define GK 32
#define KCH (H/GK)       // 24
#define NSTG 4
#define ST_SZ 24576      // Ahi 8K | Alo 8K | B 8K
#define OFF_AHI 0
#define OFF_ALO 8192
#define OFF_B   16384
#define TC_SMEM (NSTG*ST_SZ)   // 96KB

__global__ __launch_bounds__(256, 2) void hmma_gemm(
    const __half* __restrict__ Ahi, const __half* __restrict__ Alo,
    const __half* __restrict__ Wh,
    const float* __restrict__ bias, __half* __restrict__ C)
{
    extern __shared__ char smem[];
    const uint32_t sb = smem_u32(smem);
    const int tid = threadIdx.x;
    const int wid = tid >> 5, lane = tid & 31;
    const int wm = wid >> 2, wn = wid & 3;        // 2 x 4 warp grid -> 64 x 32 per warp
    const int m0 = blockIdx.y * GM, n0 = blockIdx.x * GN;

    const char* aH = (const char*)(Ahi + (size_t)m0 * H);
    const char* aL = (const char*)(Alo + (size_t)m0 * H);
    const char* bW = (const char*)(Wh + (size_t)n0 * H);

    float acc[4][4][4];
    #pragma unroll
    for (int i = 0; i < 4; i++)
        #pragma unroll
        for (int j = 0; j < 4; j++)
            #pragma unroll
            for (int q = 0; q < 4; q++) acc[i][j][q] = 0.f;

    // stage loader: 3 buffers x 512 16B-chunks (128 rows x 4 chunks of 16B)
    auto load_stage = [&](int stage, int chunk) {
        uint32_t st = sb + stage * ST_SZ;
        int kb = chunk * 64;                 // byte offset in K within a row
        #pragma unroll
        for (int i = 0; i < 6; i++) {
            int buf = i >> 1;
            int rem = ((i & 1) << 8) + tid;  // 0..511
            int row = rem >> 2, ch = rem & 3;
            uint32_t off = (uint32_t)buf * 8192 + row * 64 + (((ch ^ ((row >> 1) & 3))) << 4);
            const char* base = (buf == 0) ? aH : (buf == 1) ? aL : bW;
            cp16(st + off, base + (size_t)row * (H*2) + kb + ch * 16);
        }
        cp_commit();
    };

    load_stage(0, 0);
    load_stage(1, 1);
    load_stage(2, 2);

    const int arow = lane & 15;
    const int akh  = lane >> 4;              // 0/1
    const int brow = lane & 7;
    const int bkh  = (lane >> 3) & 1;

    for (int c = 0; c < KCH; c++) {
        if (c < KCH-2) cp_wait2(); else if (c == KCH-2) cp_wait1(); else cp_wait0();
        __syncthreads();
        if (c + 3 < KCH) load_stage((c + 3) % NSTG, c + 3);

        uint32_t st = sb + (c % NSTG) * ST_SZ;
        #pragma unroll
        for (int j = 0; j < 2; j++) {        // two k16 steps per chunk
            uint32_t ah[4][4], al[4][4];
            int ka = j * 2 + akh;
            #pragma unroll
            for (int mt = 0; mt < 4; mt++) {
                int row = wm * 64 + mt * 16 + arow;
                uint32_t off = row * 64 + ((ka ^ ((row >> 1) & 3)) << 4);
                ldm_x4(ah[mt], st + OFF_AHI + off);
                ldm_x4(al[mt], st + OFF_ALO + off);
            }
            int kb2 = j * 2 + bkh;
            #pragma unroll
            for (int nt = 0; nt < 4; nt++) {
                uint32_t bh[2];
                int row = wn * 32 + nt * 8 + brow;
                uint32_t off = row * 64 + ((kb2 ^ ((row >> 1) & 3)) << 4);
                ldm_x2(bh, st + OFF_B + off);
                #pragma unroll
                for (int mt = 0; mt < 4; mt++) {
                    mma_f16(acc[mt][nt], ah[mt], bh);
                    mma_f16(acc[mt][nt], al[mt], bh);
                }
            }
        }
    }

    // epilogue: fp16 output
    const int g = lane >> 2, tq = lane & 3;
    #pragma unroll
    for (int mt = 0; mt < 4; mt++) {
        #pragma unroll
        for (int nt = 0; nt < 4; nt++) {
            int row = m0 + wm*64 + mt*16 + g;
            int col = n0 + wn*32 + nt*8 + tq*2;
            float b0 = bias[col], b1 = bias[col + 1];
            __half2 v0 = __floats2half2_rn(acc[mt][nt][0] + b0, acc[mt][nt][1] + b1);
            __half2 v1 = __floats2half2_rn(acc[mt][nt][2] + b0, acc[mt][nt][3] + b1);
            *(__half2*)&C[(size_t)row * NH2 + col] = v0;
            *(__half2*)&C[(size_t)(row + 8) * NH2 + col] = v1;
        }
    }
}

// ---------------- conversions ----------------
__global__ void k_splitA(const float* __restrict__ in, __half* __restrict__ hi,
                         __half* __restrict__ lo, int n)
{
    int i = blockIdx.x * blockDim.x + threadIdx.x;
    if (i >= n) return;
    float v = in[i];
    __half h = __float2half_rn(v);
    hi[i] = h;
    lo[i] = __float2half_rn(v - __half2float(h));
}

// W[768][6144] -> rows [rowoff..rowoff+6144) of combined WT [12288][768] fp16
__global__ void k_halfWT(const float* __restrict__ W, __half* __restrict__ WT, int rowoff)
{
    __shared__ float tile[32][33];
    int n0 = blockIdx.x * 32, k0 = blockIdx.y * 32;
    int tx = threadIdx.x, ty = threadIdx.y;
    #pragma unroll
    for (int i = ty; i < 32; i += 8)
        tile[i][tx] = W[(size_t)(k0 + i) * HH + n0 + tx];
    __syncthreads();
    #pragma unroll
    for (int i = ty; i < 32; i += 8)
        WT[(size_t)(rowoff + n0 + i) * H + k0 + tx] = __float2half_rn(tile[tx][i]);
}

__global__ void k_bias2(const float* __restrict__ bs, const float* __restrict__ bd,
                        float* __restrict__ b2)
{
    int i = blockIdx.x * blockDim.x + threadIdx.x;
    if (i < HH) b2[i] = bs[i];
    else if (i < NH2) b2[i] = bd[i - HH];
}

__global__ void k_copy(float* d, const float* s, int n){ int i = blockIdx.x*blockDim.x + threadIdx.x; if (i < n) d[i] = s[i]; }

// ---------------- CSR build (per graph; deterministic) ----------------
__global__ void k_csr(const int* __restrict__ dst, int* __restrict__ offA,
                      int* __restrict__ degA, int* __restrict__ eix)
{
    __shared__ int cnt[NPG];
    __shared__ int basep[NPG];
    int g = blockIdx.x, tid = threadIdx.x;
    if (tid < NPG) cnt[tid] = 0;
    __syncthreads();
    if (tid < EPG) {
        int e = g * EPG + tid;
        atomicAdd(&cnt[dst[e] - g * NPG], 1);
    }
    __syncthreads();
    if (tid == 0) {
        int run = g * EPG;
        for (int i = 0; i < NPG; i++) {
            basep[i] = run;
            offA[g * NPG + i] = run;
            degA[g * NPG + i] = cnt[i];
            run += cnt[i];
        }
        for (int j = 0; j < EPG; j++) {
            int e = g * EPG + j;
            int dl = dst[e] - g * NPG;
            eix[basep[dl]++] = e;
        }
    }
}

// ---------------- edge kernels ----------------
__global__ __launch_bounds__(256) void k_logits(const __half* __restrict__ f,
                                                const float* __restrict__ attn_a,
                                                const int* __restrict__ src,
                                                const int* __restrict__ dst,
                                                float* __restrict__ logits)
{
    int e = blockIdx.x;
    int h = threadIdx.x >> 5;
    int lane = threadIdx.x & 31;
    int s = src[e], d = dst[e];
    const __half2* pf = (const __half2*)(f + (size_t)s*NH2 + h*H);
    const __half2* pd = (const __half2*)(f + (size_t)d*NH2 + HH + h*H);
    const float2* pa = (const float2*)(attn_a + h*H);
    float acc = 0.f;
    #pragma unroll
    for (int i = lane; i < H/2; i += 32) {
        float2 a = __half22float2(pf[i]);
        float2 b = __half22float2(pd[i]);
        float2 w = pa[i];
        float v;
        v = a.x + b.x; v = v > 0.f ? v : 0.2f*v; acc += v * w.x;
        v = a.y + b.y; v = v > 0.f ? v : 0.2f*v; acc += v * w.y;
    }
    #pragma unroll
    for (int o = 16; o; o >>= 1) acc += __shfl_xor_sync(0xffffffffu, acc, o);
    if (lane == 0) logits[e*HEADS + h] = acc;
}

// warp per node: softmax over incoming edges, per head
__global__ __launch_bounds__(256) void k_softmax(const float* __restrict__ logits,
                                                 const int* __restrict__ offA,
                                                 const int* __restrict__ degA,
                                                 const int* __restrict__ eix,
                                                 float* __restrict__ att)
{
    int n = blockIdx.x * 8 + (threadIdx.x >> 5);
    int lane = threadIdx.x & 31;
    int off = offA[n], deg = degA[n];
    int h = lane & 7, grp = lane >> 3;
    float m = -1e30f;
    for (int j = grp; j < deg; j += 4)
        m = fmaxf(m, logits[eix[off + j]*HEADS + h]);
    m = fmaxf(m, __shfl_xor_sync(0xffffffffu, m, 8));
    m = fmaxf(m, __shfl_xor_sync(0xffffffffu, m, 16));
    float s = 0.f;
    for (int j = grp; j < deg; j += 4)
        s += expf(logits[eix[off + j]*HEADS + h] - m);
    s += __shfl_xor_sync(0xffffffffu, s, 8);
    s += __shfl_xor_sync(0xffffffffu, s, 16);
    float inv = 1.f / s;
    for (int j = grp; j < deg; j += 4) {
        int ei = eix[off + j];
        att[ei*HEADS + h] = expf(logits[ei*HEADS + h] - m) * inv;
    }
}

// block per node: hn[n] = (1/8) sum_j sum_h att[e_j,h] * fs[src_j, h*H:]
// fused: also emits fp16 hi/lo split for the next step's GEMM
__global__ __launch_bounds__(256) void k_aggregate(const float* __restrict__ att,
                                                   const __half* __restrict__ f,
                                                   const int* __restrict__ src,
                                                   const int* __restrict__ offA,
                                                   const int* __restrict__ degA,
                                                   const int* __restrict__ eix,
                                                   float* __restrict__ hnext,
                                                   __half* __restrict__ ahi,
                                                   __half* __restrict__ alo)
{
    __shared__ float coef[96*HEADS];
    __shared__ int   srcs[96];
    int n = blockIdx.x, tid = threadIdx.x;
    int off = offA[n], deg = degA[n];
    for (int idx = tid; idx < deg*HEADS; idx += 256) {
        int j = idx >> 3, h = idx & 7;
        coef[idx] = att[eix[off + j]*HEADS + h] * 0.125f;
    }
    if (tid < deg) srcs[tid] = src[eix[off + tid]];
    __syncthreads();
    #pragma unroll
    for (int i = tid; i < H; i += 256) {
        float v = 0.f;
        for (int j = 0; j < deg; j++) {
            const __half* p = f + (size_t)srcs[j]*NH2 + i;
            const float* cj = coef + j*HEADS;
            #pragma unroll
            for (int h = 0; h < HEADS; h++) v += cj[h] * __half2float(p[h*H]);
        }
        size_t o = (size_t)n*H + i;
        hnext[o] = v;
        __half hh = __float2half_rn(v);
        ahi[o] = hh;
        alo[o] = __float2half_rn(v - __half2float(hh));
    }
}

__global__ void k_attn_out(const float* __restrict__ att, const int* __restrict__ eids,
                           float* __restrict__ out)
{
    int i = blockIdx.x*blockDim.x + threadIdx.x;
    if (i >= B*N_ATOM) return;
    int e = eids[i];
    float s = 0.f;
    #pragma unroll
    for (int h = 0; h < HEADS; h++) s += att[e*HEADS + h];
    out[i] = s * 0.125f;
}

__global__ void k_gather(const float* __restrict__ hn, const int* __restrict__ vnids,
                         float* __restrict__ x)
{
    int i = blockIdx.x*blockDim.x + threadIdx.x;
    if (i >= B*H) return;
    int b = i / H, d = i - b*H;
    x[i] = hn[(size_t)vnids[b]*H + d];
}

// ---------------- fp32 SGEMM (small GRU GEMMs only) ----------------
#define BM 128
#define BN 128
#define BK 8
__global__ __launch_bounds__(256) void sgemm(const float* __restrict__ A,
                                             const float* __restrict__ Bm,
                                             const float* __restrict__ bias,
                                             float* __restrict__ C,
                                             int M, int N, int K)
{
    __shared__ float As[BK][BM];
    __shared__ float Bs[BK][BN];
    const int bx = blockIdx.x, by = blockIdx.y;
    const int tid = threadIdx.x;
    const int tx = tid & 15, ty = tid >> 4;
    const float* Ap = A + (size_t)by*BM*K;
    const float* Bp = Bm + bx*BN;
    const int aRow = tid >> 1, aCol4 = (tid & 1) * 4;
    const int bRow = tid >> 5, bCol4 = (tid & 31) * 4;
    float acc[8][8];
    #pragma unroll
    for (int i = 0; i < 8; i++)
        #pragma unroll
        for (int j = 0; j < 8; j++) acc[i][j] = 0.f;
    for (int k0 = 0; k0 < K; k0 += BK) {
        float4 av = *(const float4*)(Ap + (size_t)aRow*K + k0 + aCol4);
        As[aCol4+0][aRow] = av.x; As[aCol4+1][aRow] = av.y;
        As[aCol4+2][aRow] = av.z; As[aCol4+3][aRow] = av.w;
        float4 bv = *(const float4*)(Bp + (size_t)(k0 + bRow)*N + bCol4);
        *(float4*)&Bs[bRow][bCol4] = bv;
        __syncthreads();
        #pragma unroll
        for (int k = 0; k < BK; k++) {
            float a[8], b[8];
            #pragma unroll
            for (int i = 0; i < 8; i++) a[i] = As[k][ty*8 + i];
            #pragma unroll
            for (int j = 0; j < 8; j++) b[j] = Bs[k][tx*8 + j];
            #pragma unroll
            for (int i = 0; i < 8; i++)
                #pragma unroll
                for (int j = 0; j < 8; j++)
                    acc[i][j] += a[i] * b[j];
        }
        __syncthreads();
    }
    #pragma unroll
    for (int i = 0; i < 8; i++) {
        int row = by*BM + ty*8 + i;
        #pragma unroll
        for (int j = 0; j < 8; j++) {
            int col = bx*BN + tx*8 + j;
            C[(size_t)row*N + col] = acc[i][j] + bias[col];
        }
    }
}

__global__ void k_transpose(const float* __restrict__ in, float* __restrict__ out, int R, int C)
{
    __shared__ float tile[32][33];
    int c0 = blockIdx.x * 32, r0 = blockIdx.y * 32;
    int tx = threadIdx.x, ty = threadIdx.y;
    #pragma unroll
    for (int i = ty; i < 32; i += 8)
        tile[i][tx] = in[(size_t)(r0 + i)*C + c0 + tx];
    __syncthreads();
    #pragma unroll
    for (int i = ty; i < 32; i += 8)
        out[(size_t)(c0 + i)*R + r0 + tx] = tile[tx][i];
}

__global__ void k_gru(const float* __restrict__ gi, const float* __restrict__ gh,
                      float* __restrict__ mol, float* __restrict__ out_final)
{
    int i = blockIdx.x*blockDim.x + threadIdx.x;
    if (i >= B*H) return;
    int b = i / H, d = i - b*H;
    float ir = gi[b*G3H + d],       hr = gh[b*G3H + d];
    float iz = gi[b*G3H + H + d],   hz = gh[b*G3H + H + d];
    float in_= gi[b*G3H + 2*H + d], hn = gh[b*G3H + 2*H + d];
    float r = 1.f / (1.f + expf(-(ir + hr)));
    float z = 1.f / (1.f + expf(-(iz + hz)));
    float n = tanhf(in_ + r * hn);
    float hp = mol[i];
    float v = (1.f - z) * n + z * hp;
    v = v > 0.f ? v : 0.f;
    mol[i] = v;
    if (out_final) out_final[i] = v;
}

// ---------------- host ----------------
extern "C" void kernel_launch(void* const* d_in, const int* in_sizes, int n_in,
                              void* d_out, int out_size)
{
    const float* h_nodes  = (const float*)d_in[0];
    const float* mol_feat = (const float*)d_in[1];
    const float* W_src    = (const float*)d_in[2];
    const float* b_src    = (const float*)d_in[3];
    const float* W_dst    = (const float*)d_in[4];
    const float* b_dst    = (const float*)d_in[5];
    const float* attn_a   = (const float*)d_in[6];
    const float* W_ih     = (const float*)d_in[7];
    const float* W_hh     = (const float*)d_in[8];
    const float* b_ih     = (const float*)d_in[9];
    const float* b_hh     = (const float*)d_in[10];
    const int*   src      = (const int*)d_in[11];
    const int*   dst      = (const int*)d_in[12];
    const int*   vnids    = (const int*)d_in[13];
    const int*   eids     = (const int*)d_in[14];
    float* out = (float*)d_out;

    float *h0, *h1, *logits, *att, *mol, *x, *gi, *gh, *wT1, *wT2, *bias2;
    __half *f, *ahi, *alo, *wh;
    int *offA, *degA, *eixp;
    cudaGetSymbolAddress((void**)&f,      g_f);
    cudaGetSymbolAddress((void**)&h0,     g_hbuf0);
    cudaGetSymbolAddress((void**)&h1,     g_hbuf1);
    cudaGetSymbolAddress((void**)&logits, g_logits);
    cudaGetSymbolAddress((void**)&att,    g_att);
    cudaGetSymbolAddress((void**)&mol,    g_mol);
    cudaGetSymbolAddress((void**)&x,      g_x);
    cudaGetSymbolAddress((void**)&gi,     g_gi);
    cudaGetSymbolAddress((void**)&gh,     g_gh);
    cudaGetSymbolAddress((void**)&wT1,    g_wT1);
    cudaGetSymbolAddress((void**)&wT2,    g_wT2);
    cudaGetSymbolAddress((void**)&bias2,  g_bias2);
    cudaGetSymbolAddress((void**)&ahi,    g_ahi);
    cudaGetSymbolAddress((void**)&alo,    g_alo);
    cudaGetSymbolAddress((void**)&wh,     g_wh);
    cudaGetSymbolAddress((void**)&offA,   g_offA);
    cudaGetSymbolAddress((void**)&degA,   g_degA);
    cudaGetSymbolAddress((void**)&eixp,   g_eix);

    cudaFuncSetAttribute(hmma_gemm, cudaFuncAttributeMaxDynamicSharedMemorySize, TC_SMEM);

    k_copy<<<(B*H + 255)/256, 256>>>(mol, mol_feat, B*H);
    k_csr<<<B, 160>>>(dst, offA, degA, eixp);
    k_splitA<<<(NN*H + 255)/256, 256>>>(h_nodes, ahi, alo, NN*H);

    float* hbuf[2] = { h0, h1 };

    for (int t = 0; t < T_STEPS; t++) {
        // weight conversion into combined buffer
        dim3 wtg(HH/32, H/32);
        k_halfWT<<<wtg, dim3(32, 8)>>>(W_src + (size_t)t*H*HH, wh, 0);
        k_halfWT<<<wtg, dim3(32, 8)>>>(W_dst + (size_t)t*H*HH, wh, HH);
        k_bias2<<<(NH2 + 255)/256, 256>>>(b_src + t*HH, b_dst + t*HH, bias2);

        // one combined tensor-core GEMM: f = [fs | fd]  (fp16 out)
        dim3 gg(NH2/GN, NN/GM);   // 96 x 49
        hmma_gemm<<<gg, 256, TC_SMEM>>>(ahi, alo, wh, bias2, f);

        float* hn = hbuf[t & 1];
        k_logits<<<EE, 256>>>(f, attn_a + (size_t)t*HEADS*H, src, dst, logits);
        k_softmax<<<NN/8, 256>>>(logits, offA, degA, eixp, att);
        k_aggregate<<<NN, 256>>>(att, f, src, offA, degA, eixp, hn, ahi, alo);
        k_attn_out<<<(B*N_ATOM + 255)/256, 256>>>(att, eids, out + B*H + t*B*N_ATOM);

        // GRU on virtual nodes (fp32, tiny)
        k_gather<<<(B*H + 255)/256, 256>>>(hn, vnids, x);
        k_transpose<<<dim3(H/32, G3H/32), dim3(32, 8)>>>(W_ih + (size_t)t*G3H*H, wT1, G3H, H);
        k_transpose<<<dim3(H/32, G3H/32), dim3(32, 8)>>>(W_hh + (size_t)t*G3H*H, wT2, G3H, H);
        sgemm<<<dim3(G3H/BN, B/BM), 256>>>(x,   wT1, b_ih + t*G3H, gi, B, G3H, H);
        sgemm<<<dim3(G3H/BN, B/BM), 256>>>(mol, wT2, b_hh + t*G3H, gh, B, G3H, H);
        k_gru<<<(B*H + 255)/256, 256>>>(gi, gh, mol, (t == T_STEPS-1) ? out : nullptr);
    }
}

// round 7
// speedup vs baseline: 4.0636x; 1.3789x over previous
#include <cuda_runtime.h>
#include <cuda_fp16.h>
#include <cstdint>

#define H 768
#define HEADS 8
#define T_STEPS 3
#define B 128
#define N_ATOM 48
#define NPG 49
#define EPG 144
#define NN (B*NPG)        // 6272 nodes
#define EE (B*EPG)        // 18432 edges
#define HH (HEADS*H)      // 6144
#define NH2 (2*HH)        // 12288 combined fs|fd columns
#define G3H (3*H)         // 2304

// ---------------- scratch (__device__ globals; no allocation) ----------------
__device__ __half   g_f[(size_t)NN*NH2];      // combined [fs | fd] per node, fp16
__device__ float    g_hbuf0[(size_t)NN*H];
__device__ float    g_hbuf1[(size_t)NN*H];
__device__ float    g_logits[EE*HEADS];
__device__ float    g_att[EE*HEADS];
__device__ float    g_mol[B*H];
__device__ float    g_x[B*H];
__device__ float    g_gi[B*G3H];
__device__ float    g_gh[B*G3H];
__device__ float    g_wT1[(size_t)H*G3H];
__device__ float    g_wT2[(size_t)H*G3H];
__device__ float    g_bias2[NH2];
// fp16 buffers
__device__ __half g_ah[(size_t)NN*H];
__device__ __half g_wh[(size_t)NH2*H];   // [12288][768] transposed weights fp16
// CSR
__device__ int g_offA[NN];
__device__ int g_degA[NN];
__device__ int g_eix[EE];

// ---------------- PTX helpers ----------------
__device__ __forceinline__ uint32_t smem_u32(const void* p) {
    uint32_t a;
    asm("{ .reg .u64 t; cvta.to.shared.u64 t, %1; cvt.u32.u64 %0, t; }" : "=r"(a) : "l"(p));
    return a;
}
__device__ __forceinline__ void cp16(uint32_t saddr, const void* gptr) {
    asm volatile("cp.async.cg.shared.global [%0], [%1], 16;" :: "r"(saddr), "l"(gptr));
}
__device__ __forceinline__ void cp_commit() { asm volatile("cp.async.commit_group;"); }
__device__ __forceinline__ void cp_wait2() { asm volatile("cp.async.wait_group 2;"); }
__device__ __forceinline__ void cp_wait1() { asm volatile("cp.async.wait_group 1;"); }
__device__ __forceinline__ void cp_wait0() { asm volatile("cp.async.wait_group 0;"); }
__device__ __forceinline__ void ldm_x4(uint32_t* r, uint32_t addr) {
    asm volatile("ldmatrix.sync.aligned.m8n8.x4.shared.b16 {%0,%1,%2,%3}, [%4];"
                 : "=r"(r[0]), "=r"(r[1]), "=r"(r[2]), "=r"(r[3]) : "r"(addr));
}
__device__ __forceinline__ void ldm_x2(uint32_t* r, uint32_t addr) {
    asm volatile("ldmatrix.sync.aligned.m8n8.x2.shared.b16 {%0,%1}, [%2];"
                 : "=r"(r[0]), "=r"(r[1]) : "r"(addr));
}
__device__ __forceinline__ void mma_f16(float* c, const uint32_t* a, const uint32_t* b) {
    asm volatile(
        "mma.sync.aligned.m16n8k16.row.col.f32.f16.f16.f32 "
        "{%0,%1,%2,%3}, {%4,%5,%6,%7}, {%8,%9}, {%0,%1,%2,%3};"
        : "+f"(c[0]), "+f"(c[1]), "+f"(c[2]), "+f"(c[3])
        : "r"(a[0]), "r"(a[1]), "r"(a[2]), "r"(a[3]), "r"(b[0]), "r"(b[1]));
}

// ---------------- single-pass fp16 HMMA GEMM (combined fs|fd) ----------------
// f[NN,12288] = Ah[NN,768] @ Wh^T + bias2 ; W stored [12288][768] K-major fp16
#define GM 128
#define GN 128
#define GK 32
#define KCH (H/GK)       // 24
#define NSTG 4
#define ST_SZ 16384      // A 8K | B 8K
#define OFF_A 0
#define OFF_B 8192
#define TC_SMEM (NSTG*ST_SZ)   // 64KB

__global__ __launch_bounds__(256, 2) void hmma_gemm(
    const __half* __restrict__ Ah, const __half* __restrict__ Wh,
    const float* __restrict__ bias, __half* __restrict__ C)
{
    extern __shared__ char smem[];
    const uint32_t sb = smem_u32(smem);
    const int tid = threadIdx.x;
    const int wid = tid >> 5, lane = tid & 31;
    const int wm = wid >> 2, wn = wid & 3;        // 2 x 4 warp grid -> 64 x 32 per warp
    const int m0 = blockIdx.y * GM, n0 = blockIdx.x * GN;

    const char* aP = (const char*)(Ah + (size_t)m0 * H);
    const char* bP = (const char*)(Wh + (size_t)n0 * H);

    float acc[4][4][4];
    #pragma unroll
    for (int i = 0; i < 4; i++)
        #pragma unroll
        for (int j = 0; j < 4; j++)
            #pragma unroll
            for (int q = 0; q < 4; q++) acc[i][j][q] = 0.f;

    // stage loader: 2 buffers x 512 16B-chunks (128 rows x 4 chunks of 16B)
    auto load_stage = [&](int stage, int chunk) {
        uint32_t st = sb + stage * ST_SZ;
        int kb = chunk * 64;                 // byte offset in K within a row
        #pragma unroll
        for (int i = 0; i < 4; i++) {
            int buf = i >> 1;
            int rem = ((i & 1) << 8) + tid;  // 0..511
            int row = rem >> 2, ch = rem & 3;
            uint32_t off = (uint32_t)buf * 8192 + row * 64 + (((ch ^ ((row >> 1) & 3))) << 4);
            const char* base = (buf == 0) ? aP : bP;
            cp16(st + off, base + (size_t)row * (H*2) + kb + ch * 16);
        }
        cp_commit();
    };

    load_stage(0, 0);
    load_stage(1, 1);
    load_stage(2, 2);

    const int arow = lane & 15;
    const int akh  = lane >> 4;              // 0/1
    const int brow = lane & 7;
    const int bkh  = (lane >> 3) & 1;

    for (int c = 0; c < KCH; c++) {
        if (c < KCH-2) cp_wait2(); else if (c == KCH-2) cp_wait1(); else cp_wait0();
        __syncthreads();
        if (c + 3 < KCH) load_stage((c + 3) % NSTG, c + 3);

        uint32_t st = sb + (c % NSTG) * ST_SZ;
        #pragma unroll
        for (int j = 0; j < 2; j++) {        // two k16 steps per chunk
            uint32_t ah[4][4];
            int ka = j * 2 + akh;
            #pragma unroll
            for (int mt = 0; mt < 4; mt++) {
                int row = wm * 64 + mt * 16 + arow;
                uint32_t off = row * 64 + ((ka ^ ((row >> 1) & 3)) << 4);
                ldm_x4(ah[mt], st + OFF_A + off);
            }
            int kb2 = j * 2 + bkh;
            #pragma unroll
            for (int nt = 0; nt < 4; nt++) {
                uint32_t bh[2];
                int row = wn * 32 + nt * 8 + brow;
                uint32_t off = row * 64 + ((kb2 ^ ((row >> 1) & 3)) << 4);
                ldm_x2(bh, st + OFF_B + off);
                #pragma unroll
                for (int mt = 0; mt < 4; mt++)
                    mma_f16(acc[mt][nt], ah[mt], bh);
            }
        }
    }

    // epilogue: fp16 output
    const int g = lane >> 2, tq = lane & 3;
    #pragma unroll
    for (int mt = 0; mt < 4; mt++) {
        #pragma unroll
        for (int nt = 0; nt < 4; nt++) {
            int row = m0 + wm*64 + mt*16 + g;
            int col = n0 + wn*32 + nt*8 + tq*2;
            float b0 = bias[col], b1 = bias[col + 1];
            __half2 v0 = __floats2half2_rn(acc[mt][nt][0] + b0, acc[mt][nt][1] + b1);
            __half2 v1 = __floats2half2_rn(acc[mt][nt][2] + b0, acc[mt][nt][3] + b1);
            *(__half2*)&C[(size_t)row * NH2 + col] = v0;
            *(__half2*)&C[(size_t)(row + 8) * NH2 + col] = v1;
        }
    }
}

// ---------------- conversions ----------------
__global__ void k_halfA(const float* __restrict__ in, __half* __restrict__ o, int n)
{
    int i = blockIdx.x * blockDim.x + threadIdx.x;
    if (i < n) o[i] = __float2half_rn(in[i]);
}

// W[768][6144] -> rows [rowoff..rowoff+6144) of combined WT [12288][768] fp16
__global__ void k_halfWT(const float* __restrict__ W, __half* __restrict__ WT, int rowoff)
{
    __shared__ float tile[32][33];
    int n0 = blockIdx.x * 32, k0 = blockIdx.y * 32;
    int tx = threadIdx.x, ty = threadIdx.y;
    #pragma unroll
    for (int i = ty; i < 32; i += 8)
        tile[i][tx] = W[(size_t)(k0 + i) * HH + n0 + tx];
    __syncthreads();
    #pragma unroll
    for (int i = ty; i < 32; i += 8)
        WT[(size_t)(rowoff + n0 + i) * H + k0 + tx] = __float2half_rn(tile[tx][i]);
}

__global__ void k_bias2(const float* __restrict__ bs, const float* __restrict__ bd,
                        float* __restrict__ b2)
{
    int i = blockIdx.x * blockDim.x + threadIdx.x;
    if (i < HH) b2[i] = bs[i];
    else if (i < NH2) b2[i] = bd[i - HH];
}

__global__ void k_copy(float* d, const float* s, int n){ int i = blockIdx.x*blockDim.x + threadIdx.x; if (i < n) d[i] = s[i]; }

// ---------------- CSR build (per graph; deterministic) ----------------
__global__ void k_csr(const int* __restrict__ dst, int* __restrict__ offA,
                      int* __restrict__ degA, int* __restrict__ eix)
{
    __shared__ int cnt[NPG];
    __shared__ int basep[NPG];
    int g = blockIdx.x, tid = threadIdx.x;
    if (tid < NPG) cnt[tid] = 0;
    __syncthreads();
    if (tid < EPG) {
        int e = g * EPG + tid;
        atomicAdd(&cnt[dst[e] - g * NPG], 1);
    }
    __syncthreads();
    if (tid == 0) {
        int run = g * EPG;
        for (int i = 0; i < NPG; i++) {
            basep[i] = run;
            offA[g * NPG + i] = run;
            degA[g * NPG + i] = cnt[i];
            run += cnt[i];
        }
        for (int j = 0; j < EPG; j++) {
            int e = g * EPG + j;
            int dl = dst[e] - g * NPG;
            eix[basep[dl]++] = e;
        }
    }
}

// ---------------- edge kernels ----------------
__global__ __launch_bounds__(256) void k_logits(const __half* __restrict__ f,
                                                const float* __restrict__ attn_a,
                                                const int* __restrict__ src,
                                                const int* __restrict__ dst,
                                                float* __restrict__ logits)
{
    int e = blockIdx.x;
    int h = threadIdx.x >> 5;
    int lane = threadIdx.x & 31;
    int s = src[e], d = dst[e];
    const __half2* pf = (const __half2*)(f + (size_t)s*NH2 + h*H);
    const __half2* pd = (const __half2*)(f + (size_t)d*NH2 + HH + h*H);
    const float2* pa = (const float2*)(attn_a + h*H);
    float acc = 0.f;
    #pragma unroll
    for (int i = lane; i < H/2; i += 32) {
        float2 a = __half22float2(pf[i]);
        float2 b = __half22float2(pd[i]);
        float2 w = pa[i];
        float v;
        v = a.x + b.x; v = v > 0.f ? v : 0.2f*v; acc += v * w.x;
        v = a.y + b.y; v = v > 0.f ? v : 0.2f*v; acc += v * w.y;
    }
    #pragma unroll
    for (int o = 16; o; o >>= 1) acc += __shfl_xor_sync(0xffffffffu, acc, o);
    if (lane == 0) logits[e*HEADS + h] = acc;
}

// warp per node: softmax over incoming edges, per head
__global__ __launch_bounds__(256) void k_softmax(const float* __restrict__ logits,
                                                 const int* __restrict__ offA,
                                                 const int* __restrict__ degA,
                                                 const int* __restrict__ eix,
                                                 float* __restrict__ att)
{
    int n = blockIdx.x * 8 + (threadIdx.x >> 5);
    int lane = threadIdx.x & 31;
    int off = offA[n], deg = degA[n];
    int h = lane & 7, grp = lane >> 3;
    float m = -1e30f;
    for (int j = grp; j < deg; j += 4)
        m = fmaxf(m, logits[eix[off + j]*HEADS + h]);
    m = fmaxf(m, __shfl_xor_sync(0xffffffffu, m, 8));
    m = fmaxf(m, __shfl_xor_sync(0xffffffffu, m, 16));
    float s = 0.f;
    for (int j = grp; j < deg; j += 4)
        s += expf(logits[eix[off + j]*HEADS + h] - m);
    s += __shfl_xor_sync(0xffffffffu, s, 8);
    s += __shfl_xor_sync(0xffffffffu, s, 16);
    float inv = 1.f / s;
    for (int j = grp; j < deg; j += 4) {
        int ei = eix[off + j];
        att[ei*HEADS + h] = expf(logits[ei*HEADS + h] - m) * inv;
    }
}

// block per node: hn[n] = (1/8) sum_j sum_h att[e_j,h] * fs[src_j, h*H:]
// fused: also emits fp16 A for the next step's GEMM
__global__ __launch_bounds__(256) void k_aggregate(const float* __restrict__ att,
                                                   const __half* __restrict__ f,
                                                   const int* __restrict__ src,
                                                   const int* __restrict__ offA,
                                                   const int* __restrict__ degA,
                                                   const int* __restrict__ eix,
                                                   float* __restrict__ hnext,
                                                   __half* __restrict__ ah)
{
    __shared__ float coef[96*HEADS];
    __shared__ int   srcs[96];
    int n = blockIdx.x, tid = threadIdx.x;
    int off = offA[n], deg = degA[n];
    for (int idx = tid; idx < deg*HEADS; idx += 256) {
        int j = idx >> 3, h = idx & 7;
        coef[idx] = att[eix[off + j]*HEADS + h] * 0.125f;
    }
    if (tid < deg) srcs[tid] = src[eix[off + tid]];
    __syncthreads();
    #pragma unroll
    for (int i = tid; i < H; i += 256) {
        float v = 0.f;
        for (int j = 0; j < deg; j++) {
            const __half* p = f + (size_t)srcs[j]*NH2 + i;
            const float* cj = coef + j*HEADS;
            #pragma unroll
            for (int h = 0; h < HEADS; h++) v += cj[h] * __half2float(p[h*H]);
        }
        size_t o = (size_t)n*H + i;
        hnext[o] = v;
        ah[o] = __float2half_rn(v);
    }
}

__global__ void k_attn_out(const float* __restrict__ att, const int* __restrict__ eids,
                           float* __restrict__ out)
{
    int i = blockIdx.x*blockDim.x + threadIdx.x;
    if (i >= B*N_ATOM) return;
    int e = eids[i];
    float s = 0.f;
    #pragma unroll
    for (int h = 0; h < HEADS; h++) s += att[e*HEADS + h];
    out[i] = s * 0.125f;
}

__global__ void k_gather(const float* __restrict__ hn, const int* __restrict__ vnids,
                         float* __restrict__ x)
{
    int i = blockIdx.x*blockDim.x + threadIdx.x;
    if (i >= B*H) return;
    int b = i / H, d = i - b*H;
    x[i] = hn[(size_t)vnids[b]*H + d];
}

// ---------------- fp32 SGEMM (small GRU GEMMs only) ----------------
#define BM 128
#define BN 128
#define BK 8
__global__ __launch_bounds__(256) void sgemm(const float* __restrict__ A,
                                             const float* __restrict__ Bm,
                                             const float* __restrict__ bias,
                                             float* __restrict__ C,
                                             int M, int N, int K)
{
    __shared__ float As[BK][BM];
    __shared__ float Bs[BK][BN];
    const int bx = blockIdx.x, by = blockIdx.y;
    const int tid = threadIdx.x;
    const int tx = tid & 15, ty = tid >> 4;
    const float* Ap = A + (size_t)by*BM*K;
    const float* Bp = Bm + bx*BN;
    const int aRow = tid >> 1, aCol4 = (tid & 1) * 4;
    const int bRow = tid >> 5, bCol4 = (tid & 31) * 4;
    float acc[8][8];
    #pragma unroll
    for (int i = 0; i < 8; i++)
        #pragma unroll
        for (int j = 0; j < 8; j++) acc[i][j] = 0.f;
    for (int k0 = 0; k0 < K; k0 += BK) {
        float4 av = *(const float4*)(Ap + (size_t)aRow*K + k0 + aCol4);
        As[aCol4+0][aRow] = av.x; As[aCol4+1][aRow] = av.y;
        As[aCol4+2][aRow] = av.z; As[aCol4+3][aRow] = av.w;
        float4 bv = *(const float4*)(Bp + (size_t)(k0 + bRow)*N + bCol4);
        *(float4*)&Bs[bRow][bCol4] = bv;
        __syncthreads();
        #pragma unroll
        for (int k = 0; k < BK; k++) {
            float a[8], b[8];
            #pragma unroll
            for (int i = 0; i < 8; i++) a[i] = As[k][ty*8 + i];
            #pragma unroll
            for (int j = 0; j < 8; j++) b[j] = Bs[k][tx*8 + j];
            #pragma unroll
            for (int i = 0; i < 8; i++)
                #pragma unroll
                for (int j = 0; j < 8; j++)
                    acc[i][j] += a[i] * b[j];
        }
        __syncthreads();
    }
    #pragma unroll
    for (int i = 0; i < 8; i++) {
        int row = by*BM + ty*8 + i;
        #pragma unroll
        for (int j = 0; j < 8; j++) {
            int col = bx*BN + tx*8 + j;
            C[(size_t)row*N + col] = acc[i][j] + bias[col];
        }
    }
}

__global__ void k_transpose(const float* __restrict__ in, float* __restrict__ out, int R, int C)
{
    __shared__ float tile[32][33];
    int c0 = blockIdx.x * 32, r0 = blockIdx.y * 32;
    int tx = threadIdx.x, ty = threadIdx.y;
    #pragma unroll
    for (int i = ty; i < 32; i += 8)
        tile[i][tx] = in[(size_t)(r0 + i)*C + c0 + tx];
    __syncthreads();
    #pragma unroll
    for (int i = ty; i < 32; i += 8)
        out[(size_t)(c0 + i)*R + r0 + tx] = tile[tx][i];
}

__global__ void k_gru(const float* __restrict__ gi, const float* __restrict__ gh,
                      float* __restrict__ mol, float* __restrict__ out_final)
{
    int i = blockIdx.x*blockDim.x + threadIdx.x;
    if (i >= B*H) return;
    int b = i / H, d = i - b*H;
    float ir = gi[b*G3H + d],       hr = gh[b*G3H + d];
    float iz = gi[b*G3H + H + d],   hz = gh[b*G3H + H + d];
    float in_= gi[b*G3H + 2*H + d], hn = gh[b*G3H + 2*H + d];
    float r = 1.f / (1.f + expf(-(ir + hr)));
    float z = 1.f / (1.f + expf(-(iz + hz)));
    float n = tanhf(in_ + r * hn);
    float hp = mol[i];
    float v = (1.f - z) * n + z * hp;
    v = v > 0.f ? v : 0.f;
    mol[i] = v;
    if (out_final) out_final[i] = v;
}

// ---------------- host ----------------
extern "C" void kernel_launch(void* const* d_in, const int* in_sizes, int n_in,
                              void* d_out, int out_size)
{
    const float* h_nodes  = (const float*)d_in[0];
    const float* mol_feat = (const float*)d_in[1];
    const float* W_src    = (const float*)d_in[2];
    const float* b_src    = (const float*)d_in[3];
    const float* W_dst    = (const float*)d_in[4];
    const float* b_dst    = (const float*)d_in[5];
    const float* attn_a   = (const float*)d_in[6];
    const float* W_ih     = (const float*)d_in[7];
    const float* W_hh     = (const float*)d_in[8];
    const float* b_ih     = (const float*)d_in[9];
    const float* b_hh     = (const float*)d_in[10];
    const int*   src      = (const int*)d_in[11];
    const int*   dst      = (const int*)d_in[12];
    const int*   vnids    = (const int*)d_in[13];
    const int*   eids     = (const int*)d_in[14];
    float* out = (float*)d_out;

    float *h0, *h1, *logits, *att, *mol, *x, *gi, *gh, *wT1, *wT2, *bias2;
    __half *f, *ah, *wh;
    int *offA, *degA, *eixp;
    cudaGetSymbolAddress((void**)&f,      g_f);
    cudaGetSymbolAddress((void**)&h0,     g_hbuf0);
    cudaGetSymbolAddress((void**)&h1,     g_hbuf1);
    cudaGetSymbolAddress((void**)&logits, g_logits);
    cudaGetSymbolAddress((void**)&att,    g_att);
    cudaGetSymbolAddress((void**)&mol,    g_mol);
    cudaGetSymbolAddress((void**)&x,      g_x);
    cudaGetSymbolAddress((void**)&gi,     g_gi);
    cudaGetSymbolAddress((void**)&gh,     g_gh);
    cudaGetSymbolAddress((void**)&wT1,    g_wT1);
    cudaGetSymbolAddress((void**)&wT2,    g_wT2);
    cudaGetSymbolAddress((void**)&bias2,  g_bias2);
    cudaGetSymbolAddress((void**)&ah,     g_ah);
    cudaGetSymbolAddress((void**)&wh,     g_wh);
    cudaGetSymbolAddress((void**)&offA,   g_offA);
    cudaGetSymbolAddress((void**)&degA,   g_degA);
    cudaGetSymbolAddress((void**)&eixp,   g_eix);

    cudaFuncSetAttribute(hmma_gemm, cudaFuncAttributeMaxDynamicSharedMemorySize, TC_SMEM);

    k_copy<<<(B*H + 255)/256, 256>>>(mol, mol_feat, B*H);
    k_csr<<<B, 160>>>(dst, offA, degA, eixp);
    k_halfA<<<(NN*H + 255)/256, 256>>>(h_nodes, ah, NN*H);

    float* hbuf[2] = { h0, h1 };

    for (int t = 0; t < T_STEPS; t++) {
        // weight conversion into combined buffer
        dim3 wtg(HH/32, H/32);
        k_halfWT<<<wtg, dim3(32, 8)>>>(W_src + (size_t)t*H*HH, wh, 0);
        k_halfWT<<<wtg, dim3(32, 8)>>>(W_dst + (size_t)t*H*HH, wh, HH);
        k_bias2<<<(NH2 + 255)/256, 256>>>(b_src + t*HH, b_dst + t*HH, bias2);

        // one combined tensor-core GEMM: f = [fs | fd]  (fp16 out)
        dim3 gg(NH2/GN, NN/GM);   // 96 x 49
        hmma_gemm<<<gg, 256, TC_SMEM>>>(ah, wh, bias2, f);

        float* hn = hbuf[t & 1];
        k_logits<<<EE, 256>>>(f, attn_a + (size_t)t*HEADS*H, src, dst, logits);
        k_softmax<<<NN/8, 256>>>(logits, offA, degA, eixp, att);
        k_aggregate<<<NN, 256>>>(att, f, src, offA, degA, eixp, hn, ah);
        k_attn_out<<<(B*N_ATOM + 255)/256, 256>>>(att, eids, out + B*H + t*B*N_ATOM);

        // GRU on virtual nodes (fp32, tiny)
        k_gather<<<(B*H + 255)/256, 256>>>(hn, vnids, x);
        k_transpose<<<dim3(H/32, G3H/32), dim3(32, 8)>>>(W_ih + (size_t)t*G3H*H, wT1, G3H, H);
        k_transpose<<<dim3(H/32, G3H/32), dim3(32, 8)>>>(W_hh + (size_t)t*G3H*H, wT2, G3H, H);
        sgemm<<<dim3(G3H/BN, B/BM), 256>>>(x,   wT1, b_ih + t*G3H, gi, B, G3H, H);
        sgemm<<<dim3(G3H/BN, B/BM), 256>>>(mol, wT2, b_hh + t*G3H, gh, B, G3H, H);
        k_gru<<<(B*H + 255)/256, 256>>>(gi, gh, mol, (t == T_STEPS-1) ? out : nullptr);
    }
}